// round 10
// baseline (speedup 1.0000x reference)
#include <cuda_runtime.h>

#define NB 16
#define TT 1024
#define HH 1024
#define G3 3072
#define NPOS (NB*TT)
#define NTH_ELEMS (NB*TT*HH)
#define NCTA_W 296
#define WTHR 256
#define MAXMT 2048
#define MAXTILES 49152

typedef unsigned long long u64;

// scratch
__device__ float    g_gx[(size_t)NPOS * G3];   // 192 MB, position-ordered
__device__ float    g_rh[(size_t)NPOS * HH];
__device__ float    g_z [(size_t)NPOS * HH];
__device__ unsigned g_rbits[TT];
__device__ unsigned g_poslist[NPOS];
__device__ unsigned g_waveoff[TT + 1];
__device__ unsigned g_nwaves;
__device__ unsigned g_mtgb[TT];
__device__ unsigned g_mtidpos[NPOS];           // pos -> global mtile id
__device__ unsigned g_td0[MAXTILES];           // phase|kind<<1|ntile<<3|mtile<<7
__device__ unsigned g_td1[MAXTILES];           // base | cnt<<15
__device__ unsigned g_td2[MAXTILES];           // global mtile id
__device__ unsigned g_ntiles;
__device__ unsigned g_tnext;
__device__ unsigned g_cA[MAXMT];
__device__ unsigned g_cB[MAXMT];

// ---- packed fp32x2 helpers ----
__device__ __forceinline__ void fma2(u64& d, u64 a, u64 b) {
    asm("fma.rn.f32x2 %0, %1, %2, %0;" : "+l"(d) : "l"(a), "l"(b));
}
__device__ __forceinline__ u64 dup2(float x) {
    u64 r; asm("mov.b64 %0, {%1, %1};" : "=l"(r) : "f"(x)); return r;
}
__device__ __forceinline__ float2 unpk(u64 v) {
    float2 r; asm("mov.b64 {%0, %1}, %2;" : "=f"(r.x), "=f"(r.y) : "l"(v)); return r;
}
__device__ __forceinline__ float sigm(float x) {
    return 1.f / (1.f + __expf(-x));
}

// ---------------------------------------------------------------------------
// gx = x @ w_i  (fp32 packed FFMA2, 128x128x8, conflict-free B columns)
// ---------------------------------------------------------------------------
__global__ void __launch_bounds__(256, 2) gx_gemm_kernel(
        const float* __restrict__ A,
        const float* __restrict__ B) {
    __shared__ float As[2][8][128];
    __shared__ float Bs[2][8][128];

    const int tid = threadIdx.x;
    const int bm = blockIdx.y * 128;
    const int bn = blockIdx.x * 128;
    const int tx = tid & 15;
    const int ty = tid >> 4;

    u64 acc2[8][4];
#pragma unroll
    for (int i = 0; i < 8; i++)
#pragma unroll
        for (int j = 0; j < 4; j++) acc2[i][j] = 0ull;

    const int arow = tid >> 1;
    const int acol = (tid & 1) * 4;
    const int brow = tid >> 5;
    const int bcol = (tid & 31) * 4;
    const float* Ap = A + (size_t)(bm + arow) * HH + acol;
    const float* Bp = B + (size_t)brow * G3 + bn + bcol;

    float4 av = *(const float4*)Ap;
    float4 bv = *(const float4*)Bp;
    As[0][acol + 0][arow] = av.x;
    As[0][acol + 1][arow] = av.y;
    As[0][acol + 2][arow] = av.z;
    As[0][acol + 3][arow] = av.w;
    *(float4*)&Bs[0][brow][bcol] = bv;

    for (int it = 0; it < 128; it++) {
        __syncthreads();
        const int db = it & 1;
        if (it < 127) {
            Ap += 8;
            Bp += (size_t)8 * G3;
            av = *(const float4*)Ap;
            bv = *(const float4*)Bp;
        }
#pragma unroll
        for (int kk = 0; kk < 8; kk++) {
            float4 a0 = *(const float4*)&As[db][kk][ty * 8];
            float4 a1 = *(const float4*)&As[db][kk][ty * 8 + 4];
            ulonglong2 b01 = *(const ulonglong2*)&Bs[db][kk][tx * 4];
            ulonglong2 b23 = *(const ulonglong2*)&Bs[db][kk][64 + tx * 4];
            u64 ad[8];
            ad[0] = dup2(a0.x); ad[1] = dup2(a0.y);
            ad[2] = dup2(a0.z); ad[3] = dup2(a0.w);
            ad[4] = dup2(a1.x); ad[5] = dup2(a1.y);
            ad[6] = dup2(a1.z); ad[7] = dup2(a1.w);
#pragma unroll
            for (int i = 0; i < 8; i++) {
                fma2(acc2[i][0], ad[i], b01.x);
                fma2(acc2[i][1], ad[i], b01.y);
                fma2(acc2[i][2], ad[i], b23.x);
                fma2(acc2[i][3], ad[i], b23.y);
            }
        }
        if (it < 127) {
            const int nb = db ^ 1;
            As[nb][acol + 0][arow] = av.x;
            As[nb][acol + 1][arow] = av.y;
            As[nb][acol + 2][arow] = av.z;
            As[nb][acol + 3][arow] = av.w;
            *(float4*)&Bs[nb][brow][bcol] = bv;
        }
    }

#pragma unroll
    for (int i = 0; i < 8; i++) {
        float* Cp = g_gx + (size_t)(bm + ty * 8 + i) * G3 + bn;
        float2 c0 = unpk(acc2[i][0]);
        float2 c1 = unpk(acc2[i][1]);
        float2 c2 = unpk(acc2[i][2]);
        float2 c3 = unpk(acc2[i][3]);
        *(float4*)(Cp + tx * 4)      = make_float4(c0.x, c0.y, c1.x, c1.y);
        *(float4*)(Cp + 64 + tx * 4) = make_float4(c2.x, c2.y, c3.x, c3.y);
    }
}

// ---------------------------------------------------------------------------
// setup: reset sniff, bitmasks, wave decomposition, tile list, dep counters
// ---------------------------------------------------------------------------
__global__ void setup_kernel(const void* __restrict__ reset_raw,
                             const float* __restrict__ initial_h,
                             float* __restrict__ out) {
    __shared__ unsigned hist[TT];
    __shared__ unsigned curs[TT];
    __shared__ unsigned rbs[TT];
    __shared__ unsigned short depth[NB][TT];
    __shared__ int s_i32, s_f32;
    const int tid = threadIdx.x;
    if (tid == 0) { s_i32 = 1; s_f32 = 1; }
    __syncthreads();
    {
        const unsigned* rw = (const unsigned*)reset_raw;
        int bad_i = 0, bad_f = 0;
        for (int q = tid; q < 4096; q += 256) {
            unsigned v = rw[q];
            if (v > 1u) bad_i = 1;
            if (v != 0u && v != 0x3F800000u) bad_f = 1;
        }
        if (bad_i) s_i32 = 0;
        if (bad_f) s_f32 = 0;
    }
    __syncthreads();
    const int rmode = s_i32 ? 0 : (s_f32 ? 1 : 2);
    const int*           r32 = (const int*)reset_raw;
    const float*         rf  = (const float*)reset_raw;
    const unsigned char* r8  = (const unsigned char*)reset_raw;

    for (int t = tid; t < TT; t += 256) {
        unsigned m = 0;
#pragma unroll
        for (int n = 0; n < NB; n++) {
            bool rv = (rmode == 0) ? (r32[n * TT + t] != 0)
                    : (rmode == 1) ? (rf[n * TT + t] != 0.f)
                                   : (r8[n * TT + t] != 0);
            m |= (unsigned)rv << n;
        }
        rbs[t] = m;
        g_rbits[t] = m;
        hist[t] = 0;
    }
    for (int i = tid; i < MAXMT; i += 256) { g_cA[i] = 0u; g_cB[i] = 0u; }
    if (tid == 0) g_tnext = 0u;
    __syncthreads();
    if (tid < NB) {
        unsigned short d = 0;
        for (int t = 0; t < TT; t++) {
            if (t == 0 || ((rbs[t] >> tid) & 1u)) d = 0; else d++;
            depth[tid][t] = d;
            atomicAdd(&hist[d], 1u);
        }
    }
    __syncthreads();
    if (tid == 0) {
        unsigned acc = 0, maxd = 0;
        for (int w0 = 0; w0 < TT; w0++) {
            unsigned c = hist[w0];
            if (c) maxd = (unsigned)w0;
            curs[w0] = acc;
            g_waveoff[w0] = acc;
            acc += c;
        }
        g_waveoff[TT] = acc;
        g_nwaves = maxd + 1;

        // build topologically ordered tile list
        unsigned ntl = 0, mtg = 0;
        for (unsigned w = 0; w <= maxd; w++) {
            unsigned b = g_waveoff[w], c = g_waveoff[w + 1] - b;
            int kind = (c >= 1536) ? 2 : (c >= 256 ? 1 : 0);
            int posb = (kind == 2) ? 128 : (kind == 1 ? 64 : 16);
            int mt = (int)((c + posb - 1) / posb);
            for (int m = 0; m < mt; m++)
                for (int n = 0; n < 16; n++) {
                    g_td0[ntl] = 0u | ((unsigned)kind << 1) |
                                 ((unsigned)n << 3) | ((unsigned)m << 7);
                    g_td1[ntl] = b | (c << 15);
                    g_td2[ntl] = mtg + m;
                    ntl++;
                }
            for (int m = 0; m < mt; m++)
                for (int n = 0; n < 8; n++) {
                    g_td0[ntl] = 1u | ((unsigned)kind << 1) |
                                 ((unsigned)n << 3) | ((unsigned)m << 7);
                    g_td1[ntl] = b | (c << 15);
                    g_td2[ntl] = mtg + m;
                    ntl++;
                }
            g_mtgb[w] = mtg;
            mtg += mt;
        }
        g_ntiles = ntl;
    }
    __syncthreads();
    for (int p = tid; p < NPOS; p += 256) {
        int n = p >> 10, t = p & 1023;
        unsigned d = depth[n][t];
        unsigned slot = atomicAdd(&curs[d], 1u);
        g_poslist[slot] = (unsigned)p;
    }
    __syncthreads();
    // pos -> global mtile id of its slot
    {
        unsigned nw = g_nwaves;
        for (unsigned w = 0; w < nw; w++) {
            unsigned b = g_waveoff[w], c = g_waveoff[w + 1] - b;
            int kind = (c >= 1536) ? 2 : (c >= 256 ? 1 : 0);
            int posb = (kind == 2) ? 128 : (kind == 1 ? 64 : 16);
            unsigned mg = g_mtgb[w];
            for (unsigned s = b + tid; s < b + c; s += 256)
                g_mtidpos[g_poslist[s]] = mg + (s - b) / (unsigned)posb;
        }
    }
    for (int q = tid; q < HH; q += 256)
        out[2 * (size_t)NTH_ELEMS + q] = initial_h[q];
}

// ---------------------------------------------------------------------------
struct WaveCtx {
    const float* carry;
    const float* initial_h;
    const float* w_h;
    const float* bias;
    float* out;
    float* AsRaw;                 // union: As8[2][16][132] / As[2][32][64]
    float (*Bs)[32][128];
    const unsigned* rbs;
    const float** rowp;
    unsigned* posv;
    volatile unsigned* bc;
};

// set_rows with per-row dependency wait (prev position's h must be complete)
__device__ __forceinline__ void set_rows(const WaveCtx& C, int phase,
                                         int mtile, int POSB,
                                         unsigned base, unsigned cnt) {
    const int tid = threadIdx.x;
    __syncthreads();
    int need = 0;
    unsigned mtprev = 0;
    if (tid < POSB) {
        int idx = mtile * POSB + tid;
        unsigned pos = 0xFFFFFFFFu;
        const float* rp = C.initial_h;
        if ((unsigned)idx < cnt) {
            pos = g_poslist[base + idx];
            int n = pos >> 10, t = (int)(pos & 1023);
            if (phase)
                rp = g_rh + (size_t)pos * HH;
            else if ((C.rbs[t] >> n) & 1u)
                rp = C.initial_h;
            else if (t == 0)
                rp = C.carry + (size_t)n * TT * HH;
            else {
                rp = C.out + (size_t)(pos - 1) * HH;
                need = 1;
                mtprev = g_mtidpos[pos - 1];
            }
        }
        C.posv[tid] = pos;
        C.rowp[tid] = rp;
    }
    for (;;) {
        int ok = 1;
        if (need) {
            unsigned v;
            asm volatile("ld.acquire.gpu.global.u32 %0, [%1];"
                         : "=r"(v) : "l"(&g_cB[mtprev]) : "memory");
            ok = (v >= 8u);
        }
        if (__syncthreads_and(ok)) break;
        __nanosleep(100);
    }
}

// ---- epilogue for one 4-column segment ----
__device__ __forceinline__ void epi_seg(const WaveCtx& C, int phase,
                                        unsigned pos, int col0,
                                        const float* rowptr,
                                        u64 q0, u64 q1) {
    float2 f0 = unpk(q0), f1 = unpk(q1);
    float res[4] = {f0.x, f0.y, f1.x, f1.y};
    float4 gx0 = __ldcg((const float4*)(g_gx + (size_t)pos * G3 + col0));
    float gg[4] = {gx0.x, gx0.y, gx0.z, gx0.w};
    float4 bb0 = *(const float4*)(C.bias + col0);
    float bb[4] = {bb0.x, bb0.y, bb0.z, bb0.w};

    if (phase == 0 && col0 < HH) {                 // z-gate
        float o[4];
#pragma unroll
        for (int s = 0; s < 4; s++) o[s] = sigm(gg[s] + res[s] + bb[s]);
        *(float4*)(g_z + (size_t)pos * HH + col0) =
            make_float4(o[0], o[1], o[2], o[3]);
    } else if (phase == 0) {                       // r-gate -> rh
        const int j0 = col0 - HH;
        float4 h0 = __ldcg((const float4*)(rowptr + j0));
        float hh[4] = {h0.x, h0.y, h0.z, h0.w};
        float o[4];
#pragma unroll
        for (int s = 0; s < 4; s++)
            o[s] = sigm(gg[s] + res[s] + bb[s]) * hh[s];
        *(float4*)(g_rh + (size_t)pos * HH + j0) =
            make_float4(o[0], o[1], o[2], o[3]);
    } else {                                       // a-gate -> h_out
        const int j0 = col0 - 2 * HH;
        int n = pos >> 10, t = (int)(pos & 1023);
        const float* hp = ((C.rbs[t] >> n) & 1u) ? C.initial_h
                        : (t == 0 ? C.carry + (size_t)n * TT * HH
                                  : C.out + (size_t)(pos - 1) * HH);
        float4 h0 = __ldcg((const float4*)(hp + j0));
        float hh[4] = {h0.x, h0.y, h0.z, h0.w};
        float4 z0 = __ldcg((const float4*)(g_z + (size_t)pos * HH + j0));
        float zz[4] = {z0.x, z0.y, z0.z, z0.w};
        float o[4];
#pragma unroll
        for (int s = 0; s < 4; s++) {
            float a = tanhf(gg[s] + res[s] + bb[s]);
            o[s] = (1.f - zz[s]) * hh[s] + zz[s] * a;
        }
        float* op = C.out + (size_t)pos * HH + j0;
        float4 v = make_float4(o[0], o[1], o[2], o[3]);
        *(float4*)op               = v;
        *(float4*)(op + NTH_ELEMS) = v;
    }
}

__device__ __forceinline__ void epilogue_row(const WaveCtx& C, int phase,
                                             int colbase, int tx,
                                             unsigned pos,
                                             const float* rowptr,
                                             const u64* accq) {
    epi_seg(C, phase, pos, colbase + tx * 4,      rowptr, accq[0], accq[1]);
    epi_seg(C, phase, pos, colbase + 64 + tx * 4, rowptr, accq[2], accq[3]);
}

// ---------------------------------------------------------------------------
// big tile: 128 gathered rows x 128 cols, K=1024, kt=16, 8x8 per thread
// ---------------------------------------------------------------------------
#define AS8_STRIDE 132
__device__ void gemm_tile8(const WaveCtx& C, int phase, int mtile, int ntile,
                           unsigned base, unsigned cnt) {
    const int tid = threadIdx.x;
    const int tx = tid & 15;
    const int ty = tid >> 4;
    float* As8 = C.AsRaw;
    float (*Bs8)[16][128] = (float(*)[16][128])C.Bs;

    set_rows(C, phase, mtile, 128, base, cnt);

    const int colbase = (phase ? 2 * HH : 0) + ntile * 128;
    const float* wb = C.w_h + colbase;

    u64 acc[8][4];
#pragma unroll
    for (int r = 0; r < 8; r++)
#pragma unroll
        for (int j = 0; j < 4; j++) acc[r][j] = 0ull;

    float4 aL[2], bL[2];
    auto loadA = [&](int k0) {
#pragma unroll
        for (int p = 0; p < 2; p++) {
            int q = tid + 256 * p;
            int r = q >> 2, c4 = q & 3;
            aL[p] = __ldcg((const float4*)(C.rowp[r] + k0 + c4 * 4));
        }
    };
    auto storeA = [&](int buf) {
        float* bp = As8 + buf * 16 * AS8_STRIDE;
#pragma unroll
        for (int p = 0; p < 2; p++) {
            int q = tid + 256 * p;
            int r = q >> 2, c4 = q & 3;
            bp[(c4 * 4 + 0) * AS8_STRIDE + r] = aL[p].x;
            bp[(c4 * 4 + 1) * AS8_STRIDE + r] = aL[p].y;
            bp[(c4 * 4 + 2) * AS8_STRIDE + r] = aL[p].z;
            bp[(c4 * 4 + 3) * AS8_STRIDE + r] = aL[p].w;
        }
    };
    auto loadB = [&](int k0) {
#pragma unroll
        for (int p = 0; p < 2; p++) {
            int q = tid + 256 * p;
            int krow = q >> 5, col4 = q & 31;
            bL[p] = __ldcg((const float4*)(wb + (size_t)(k0 + krow) * G3 + col4 * 4));
        }
    };
    auto storeB = [&](int buf) {
#pragma unroll
        for (int p = 0; p < 2; p++) {
            int q = tid + 256 * p;
            int krow = q >> 5, col4 = q & 31;
            *(float4*)&Bs8[buf][krow][col4 * 4] = bL[p];
        }
    };

    loadA(0); loadB(0);
    storeA(0); storeB(0);
    for (int it = 0; it < 64; it++) {
        __syncthreads();
        const int db = it & 1;
        if (it < 63) { loadA((it + 1) * 16); loadB((it + 1) * 16); }
        const float* ab = As8 + db * 16 * AS8_STRIDE;
#pragma unroll
        for (int kk = 0; kk < 16; kk++) {
            float4 a0 = *(const float4*)(ab + kk * AS8_STRIDE + ty * 8);
            float4 a1 = *(const float4*)(ab + kk * AS8_STRIDE + ty * 8 + 4);
            ulonglong2 b01 = *(const ulonglong2*)&Bs8[db][kk][tx * 4];
            ulonglong2 b23 = *(const ulonglong2*)&Bs8[db][kk][64 + tx * 4];
            float av[8] = {a0.x, a0.y, a0.z, a0.w, a1.x, a1.y, a1.z, a1.w};
#pragma unroll
            for (int r = 0; r < 8; r++) {
                u64 ar = dup2(av[r]);
                fma2(acc[r][0], ar, b01.x);
                fma2(acc[r][1], ar, b01.y);
                fma2(acc[r][2], ar, b23.x);
                fma2(acc[r][3], ar, b23.y);
            }
        }
        if (it < 63) { const int nb = db ^ 1; storeA(nb); storeB(nb); }
    }

#pragma unroll
    for (int r = 0; r < 8; r++) {
        const int i = ty * 8 + r;
        unsigned pos = C.posv[i];
        if (pos == 0xFFFFFFFFu) continue;
        epilogue_row(C, phase, colbase, tx, pos, C.rowp[i], acc[r]);
    }
}

// ---------------------------------------------------------------------------
// medium/small tile: POSB (=R*16) rows x 128 cols, K=1024, kt=32
// ---------------------------------------------------------------------------
template<int R>
__device__ void gemm_tile(const WaveCtx& C, int phase, int mtile, int ntile,
                          unsigned base, unsigned cnt) {
    constexpr int POSB = R * 16;
    const int tid = threadIdx.x;
    const int tx = tid & 15;
    const int ty = tid >> 4;
    float (*As)[32][64] = (float(*)[32][64])C.AsRaw;

    set_rows(C, phase, mtile, POSB, base, cnt);

    const int colbase = (phase ? 2 * HH : 0) + ntile * 128;
    const float* wb = C.w_h + colbase;

    u64 acc[R][4];
#pragma unroll
    for (int r = 0; r < R; r++)
#pragma unroll
        for (int j = 0; j < 4; j++) acc[r][j] = 0ull;

    float4 aL[2], bL[4];
    auto loadA = [&](int k0) {
        if (R == 4) {
#pragma unroll
            for (int c = 0; c < 2; c++) {
                int q = tid + 256 * c;
                int i = q & 63, kc = q >> 6;
                aL[c] = __ldcg((const float4*)(C.rowp[i] + k0 + kc * 4));
            }
        } else {
            if (tid < 128) {
                int i = tid & 15, kc = tid >> 4;
                aL[0] = __ldcg((const float4*)(C.rowp[i] + k0 + kc * 4));
            }
        }
    };
    auto storeA = [&](int buf) {
        if (R == 4) {
#pragma unroll
            for (int c = 0; c < 2; c++) {
                int q = tid + 256 * c;
                int i = q & 63, kc = q >> 6;
                As[buf][kc * 4 + 0][i] = aL[c].x;
                As[buf][kc * 4 + 1][i] = aL[c].y;
                As[buf][kc * 4 + 2][i] = aL[c].z;
                As[buf][kc * 4 + 3][i] = aL[c].w;
            }
        } else {
            if (tid < 128) {
                int i = tid & 15, kc = tid >> 4;
                As[buf][kc * 4 + 0][i] = aL[0].x;
                As[buf][kc * 4 + 1][i] = aL[0].y;
                As[buf][kc * 4 + 2][i] = aL[0].z;
                As[buf][kc * 4 + 3][i] = aL[0].w;
            }
        }
    };
    auto loadB = [&](int k0) {
#pragma unroll
        for (int c = 0; c < 4; c++) {
            int q = tid + 256 * c;
            int row = q >> 5, c4 = q & 31;
            bL[c] = __ldcg((const float4*)(wb + (size_t)(k0 + row) * G3 + c4 * 4));
        }
    };
    auto storeB = [&](int buf) {
#pragma unroll
        for (int c = 0; c < 4; c++) {
            int q = tid + 256 * c;
            int row = q >> 5, c4 = q & 31;
            *(float4*)&C.Bs[buf][row][c4 * 4] = bL[c];
        }
    };

    loadA(0); loadB(0);
    storeA(0); storeB(0);
    for (int it = 0; it < 32; it++) {
        __syncthreads();
        const int db = it & 1;
        if (it < 31) { loadA((it + 1) * 32); loadB((it + 1) * 32); }
#pragma unroll
        for (int kk = 0; kk < 32; kk++) {
            float av[R];
            if (R == 4) {
                float4 a4 = *(const float4*)&As[db][kk][ty * 4];
                av[0] = a4.x; av[1] = a4.y; av[2] = a4.z; av[3] = a4.w;
            } else {
                av[0] = As[db][kk][ty];
            }
            ulonglong2 b01 = *(const ulonglong2*)&C.Bs[db][kk][tx * 4];
            ulonglong2 b23 = *(const ulonglong2*)&C.Bs[db][kk][64 + tx * 4];
#pragma unroll
            for (int r = 0; r < R; r++) {
                u64 ar = dup2(av[r]);
                fma2(acc[r][0], ar, b01.x);
                fma2(acc[r][1], ar, b01.y);
                fma2(acc[r][2], ar, b23.x);
                fma2(acc[r][3], ar, b23.y);
            }
        }
        if (it < 31) { const int nb = db ^ 1; storeA(nb); storeB(nb); }
    }

#pragma unroll
    for (int r = 0; r < R; r++) {
        const int i = ty * R + r;
        unsigned pos = C.posv[i];
        if (pos == 0xFFFFFFFFu) continue;
        epilogue_row(C, phase, colbase, tx, pos, C.rowp[i], acc[r]);
    }
}

// ---------------------------------------------------------------------------
// dataflow wave kernel: CTAs claim tiles in topological order; per-tile
// readiness via g_cA/g_cB counters. No global barriers.
// ---------------------------------------------------------------------------
__global__ void __launch_bounds__(WTHR, 2) wave_kernel(
        const float* __restrict__ carry,
        const float* __restrict__ initial_h,
        const float* __restrict__ w_h,
        const float* __restrict__ bias,
        float* __restrict__ out) {
    extern __shared__ char smw[];
    WaveCtx C;
    C.AsRaw = (float*)smw;                              // 16896 B
    C.Bs    = (float(*)[32][128])(smw + 16896);         // 32768 B
    unsigned* rbs = (unsigned*)(smw + 49664);           //  4096 B
    C.rowp  = (const float**)(smw + 53760);             //  1024 B
    C.posv  = (unsigned*)(smw + 54784);                 //   512 B
    C.bc    = (volatile unsigned*)(smw + 55296);        //    64 B
    C.rbs = rbs;
    C.carry = carry; C.initial_h = initial_h;
    C.w_h = w_h; C.bias = bias; C.out = out;

    const int tid = threadIdx.x;
    for (int t = tid; t < TT; t += WTHR) rbs[t] = g_rbits[t];
    const unsigned ntl = g_ntiles;
    __syncthreads();

    for (;;) {
        // claim next tile (in topological order)
        __syncthreads();
        if (tid == 0) C.bc[0] = atomicAdd(&g_tnext, 1u);
        __syncthreads();
        unsigned t = C.bc[0];
        if (t >= ntl) break;

        const unsigned d0 = g_td0[t];
        const unsigned d1 = g_td1[t];
        const unsigned mtg = g_td2[t];
        const int phase = (int)(d0 & 1u);
        const int kind  = (int)((d0 >> 1) & 3u);
        const int ntile = (int)((d0 >> 3) & 15u);
        const int mtile = (int)(d0 >> 7);
        const unsigned base = d1 & 0x7FFFu;
        const unsigned cnt  = d1 >> 15;

        // phase B waits for all 16 phase-A tiles of this mtile
        if (phase) {
            for (;;) {
                if (tid == 0) {
                    unsigned v;
                    asm volatile("ld.acquire.gpu.global.u32 %0, [%1];"
                                 : "=r"(v) : "l"(&g_cA[mtg]) : "memory");
                    C.bc[1] = (v >= 16u) ? 1u : 0u;
                }
                __syncthreads();
                unsigned ok = C.bc[1];
                __syncthreads();
                if (ok) break;
                __nanosleep(150);
            }
        }

        if (kind == 2)      gemm_tile8(C, phase, mtile, ntile, base, cnt);
        else if (kind == 1) gemm_tile<4>(C, phase, mtile, ntile, base, cnt);
        else                gemm_tile<1>(C, phase, mtile, ntile, base, cnt);

        // publish completion
        __threadfence();
        __syncthreads();
        if (tid == 0) {
            unsigned* cp = phase ? &g_cB[mtg] : &g_cA[mtg];
            asm volatile("red.release.gpu.global.add.u32 [%0], 1;"
                         :: "l"(cp) : "memory");
        }
    }
}

// ---------------------------------------------------------------------------
extern "C" void kernel_launch(void* const* d_in, const int* in_sizes, int n_in,
                              void* d_out, int out_size) {
    const float* x         = (const float*)d_in[0];
    const void*  reset     = d_in[1];
    const float* carry     = (const float*)d_in[2];
    const float* initial_h = (const float*)d_in[3];
    const float* w_i       = (const float*)d_in[4];
    const float* w_h       = (const float*)d_in[5];
    const float* b         = (const float*)d_in[6];
    float*       out       = (float*)d_out;
    (void)in_sizes; (void)n_in; (void)out_size;

    // order: gx (independent), setup, wave — puts wave at ncu -s 5 slot
    dim3 ggrid(G3 / 128, (NB * TT) / 128);
    gx_gemm_kernel<<<ggrid, 256>>>(x, w_i);

    setup_kernel<<<1, 256>>>(reset, initial_h, out);

    size_t smem = 55360;
    cudaFuncSetAttribute((const void*)wave_kernel,
                         cudaFuncAttributeMaxDynamicSharedMemorySize, (int)smem);
    wave_kernel<<<NCTA_W, WTHR, smem>>>(carry, initial_h, w_h, b, out);
}

// round 12
// speedup vs baseline: 1.2068x; 1.2068x over previous
#include <cuda_runtime.h>
#include <cuda_bf16.h>

#define NB 16
#define TT 1024
#define HH 1024
#define G3 3072
#define NPOS (NB*TT)
#define NTH_ELEMS (NB*TT*HH)
#define NCTA_W 296
#define WTHR 256

typedef unsigned long long u64;

// scratch
__device__ float          g_gx[(size_t)NPOS * G3];   // 192 MB, position-ordered
__device__ float          g_rh[(size_t)NPOS * HH];
__device__ float          g_z [(size_t)NPOS * HH];
__device__ __nv_bfloat16  g_xh[(size_t)NPOS * HH];   // x hi split
__device__ __nv_bfloat16  g_xl[(size_t)NPOS * HH];   // x lo split
__device__ __nv_bfloat16  g_wth[(size_t)G3 * HH];    // w_i^T hi [3072][1024]
__device__ __nv_bfloat16  g_wtl[(size_t)G3 * HH];    // w_i^T lo
__device__ unsigned g_rbits[TT];
__device__ unsigned g_poslist[NPOS];
__device__ unsigned g_waveoff[TT + 1];
__device__ unsigned g_nwaves;
__device__ unsigned g_bar;

// ---- packed fp32x2 helpers ----
__device__ __forceinline__ void fma2(u64& d, u64 a, u64 b) {
    asm("fma.rn.f32x2 %0, %1, %2, %0;" : "+l"(d) : "l"(a), "l"(b));
}
__device__ __forceinline__ u64 dup2(float x) {
    u64 r; asm("mov.b64 %0, {%1, %1};" : "=l"(r) : "f"(x)); return r;
}
__device__ __forceinline__ float2 unpk(u64 v) {
    float2 r; asm("mov.b64 {%0, %1}, %2;" : "=f"(r.x), "=f"(r.y) : "l"(v)); return r;
}
__device__ __forceinline__ float sigm(float x) {
    return 1.f / (1.f + __expf(-x));
}
__device__ __forceinline__ unsigned su32(const void* p) {
    unsigned a;
    asm("{ .reg .u64 t; cvta.to.shared.u64 t, %1; cvt.u32.u64 %0, t; }"
        : "=r"(a) : "l"(p));
    return a;
}

// ---- mma.sync helpers (baseline ISA: legal on compute_103) ----
__device__ __forceinline__ void ldm_x4(unsigned addr, unsigned r[4]) {
    asm volatile("ldmatrix.sync.aligned.m8n8.x4.shared.b16 {%0,%1,%2,%3}, [%4];"
        : "=r"(r[0]), "=r"(r[1]), "=r"(r[2]), "=r"(r[3]) : "r"(addr));
}
__device__ __forceinline__ void mma16816(float d[4], const unsigned a[4],
                                         unsigned b0, unsigned b1) {
    asm volatile(
        "mma.sync.aligned.m16n8k16.row.col.f32.bf16.bf16.f32 "
        "{%0,%1,%2,%3}, {%4,%5,%6,%7}, {%8,%9}, {%0,%1,%2,%3};"
        : "+f"(d[0]), "+f"(d[1]), "+f"(d[2]), "+f"(d[3])
        : "r"(a[0]), "r"(a[1]), "r"(a[2]), "r"(a[3]), "r"(b0), "r"(b1));
}

// ---------------------------------------------------------------------------
// prep: bf16 hi/lo split of x; transpose+split w_i
// ---------------------------------------------------------------------------
__global__ void prep_kernel(const float* __restrict__ x,
                            const float* __restrict__ w_i) {
    const size_t stride = (size_t)gridDim.x * blockDim.x;
    size_t i0 = (size_t)blockIdx.x * blockDim.x + threadIdx.x;
    for (size_t i = i0; i < (size_t)NPOS * HH; i += stride) {
        float v = x[i];
        __nv_bfloat16 h = __float2bfloat16(v);
        g_xh[i] = h;
        g_xl[i] = __float2bfloat16(v - __bfloat162float(h));
    }
    for (size_t i = i0; i < (size_t)G3 * HH; i += stride) {
        size_t k = i / G3, n = i % G3;
        float v = w_i[i];
        __nv_bfloat16 h = __float2bfloat16(v);
        g_wth[n * HH + k] = h;
        g_wtl[n * HH + k] = __float2bfloat16(v - __bfloat162float(h));
    }
}

// ---------------------------------------------------------------------------
// gx via mma.sync bf16x3: CTA 128x128, warp 32m x 64n, K-chunk 32, 2-buf
// smem row stride 40 bf16 (80B) -> conflict-free ldmatrix
// ---------------------------------------------------------------------------
#define STRD 40
#define GX_SMEM 81920

__global__ void __launch_bounds__(256, 1) gx_mma_kernel() {
    extern __shared__ __nv_bfloat16 sb[];
    const int tid = threadIdx.x;
    const int lane = tid & 31;
    const int wid = tid >> 5;
    const int wm = wid >> 1;      // 0..3
    const int wn = wid & 1;       // 0..1
    const int m0 = blockIdx.y * 128;
    const int n0 = blockIdx.x * 128;

    // regions (elements): Ah@0, Al@10240, Bh@20480, Bl@30720  ([2][128][40])
    __nv_bfloat16* Ah = sb;
    __nv_bfloat16* Al = sb + 10240;
    __nv_bfloat16* Bh = sb + 20480;
    __nv_bfloat16* Bl = sb + 30720;
    const unsigned aAh = su32(Ah);
    const unsigned aBh = su32(Bh);

    float d[2][8][4];
#pragma unroll
    for (int mt = 0; mt < 2; mt++)
#pragma unroll
        for (int nt = 0; nt < 8; nt++)
#pragma unroll
            for (int j = 0; j < 4; j++) d[mt][nt][j] = 0.f;

    // per-thread ldmatrix address parts (bytes)
    const unsigned aoff = (unsigned)(((lane & 15) * STRD + (lane >> 4) * 8) * 2);
    const unsigned boff = (unsigned)(((((lane & 7) + ((lane >> 4) << 3)) * STRD) +
                                     (((lane >> 3) & 1) * 8)) * 2);

    uint4 rah[2], ral[2], rbh[2], rbl[2];
    auto loadAB = [&](int kc0) {
#pragma unroll
        for (int p = 0; p < 2; p++) {
            int q = tid + 256 * p;
            int r = q >> 2, sg = q & 3;
            size_t offa = (size_t)(m0 + r) * HH + kc0 + sg * 8;
            size_t offb = (size_t)(n0 + r) * HH + kc0 + sg * 8;
            rah[p] = *(const uint4*)(g_xh + offa);
            ral[p] = *(const uint4*)(g_xl + offa);
            rbh[p] = *(const uint4*)(g_wth + offb);
            rbl[p] = *(const uint4*)(g_wtl + offb);
        }
    };
    auto storeAB = [&](int buf) {
#pragma unroll
        for (int p = 0; p < 2; p++) {
            int q = tid + 256 * p;
            int r = q >> 2, sg = q & 3;
            int so = buf * 5120 + r * STRD + sg * 8;
            *(uint4*)(Ah + so) = rah[p];
            *(uint4*)(Al + so) = ral[p];
            *(uint4*)(Bh + so) = rbh[p];
            *(uint4*)(Bl + so) = rbl[p];
        }
    };

    loadAB(0);
    storeAB(0);

    for (int ch = 0; ch < 32; ch++) {
        __syncthreads();
        const int db = ch & 1;
        if (ch < 31) loadAB((ch + 1) * 32);

#pragma unroll
        for (int ks = 0; ks < 2; ks++) {
            unsigned ah[2][4], al[2][4];
#pragma unroll
            for (int mt = 0; mt < 2; mt++) {
                unsigned base = aAh + (unsigned)(db * 10240 +
                                (wm * 32 + mt * 16) * 80 + ks * 32) + aoff;
                ldm_x4(base, ah[mt]);
                ldm_x4(base + 20480u, al[mt]);   // Al region = Ah + 20480 bytes
            }
#pragma unroll
            for (int bt = 0; bt < 4; bt++) {
                unsigned bh[4], bl[4];
                unsigned baseb = aBh + (unsigned)(db * 10240 +
                                 (wn * 64 + bt * 16) * 80 + ks * 32) + boff;
                ldm_x4(baseb, bh);
                ldm_x4(baseb + 20480u, bl);      // Bl region = Bh + 20480 bytes
#pragma unroll
                for (int mt = 0; mt < 2; mt++) {
                    mma16816(d[mt][bt * 2],     ah[mt], bh[0], bh[1]);
                    mma16816(d[mt][bt * 2],     ah[mt], bl[0], bl[1]);
                    mma16816(d[mt][bt * 2],     al[mt], bh[0], bh[1]);
                    mma16816(d[mt][bt * 2 + 1], ah[mt], bh[2], bh[3]);
                    mma16816(d[mt][bt * 2 + 1], ah[mt], bl[2], bl[3]);
                    mma16816(d[mt][bt * 2 + 1], al[mt], bh[2], bh[3]);
                }
            }
        }
        if (ch < 31) storeAB(db ^ 1);
    }

    // epilogue: fp32 accumulators -> g_gx
#pragma unroll
    for (int mt = 0; mt < 2; mt++) {
        int row = m0 + wm * 32 + mt * 16 + (lane >> 2);
#pragma unroll
        for (int nt = 0; nt < 8; nt++) {
            int col = n0 + wn * 64 + nt * 8 + (lane & 3) * 2;
            float* p0 = g_gx + (size_t)row * G3 + col;
            *(float2*)p0            = make_float2(d[mt][nt][0], d[mt][nt][1]);
            *(float2*)(p0 + 8 * G3) = make_float2(d[mt][nt][2], d[mt][nt][3]);
        }
    }
}

// ---------------------------------------------------------------------------
// setup: reset sniff, bitmasks, wave decomposition (R9, unchanged)
// ---------------------------------------------------------------------------
__global__ void setup_kernel(const void* __restrict__ reset_raw,
                             const float* __restrict__ initial_h,
                             float* __restrict__ out) {
    __shared__ unsigned hist[TT];
    __shared__ unsigned curs[TT];
    __shared__ unsigned rbs[TT];
    __shared__ unsigned short depth[NB][TT];
    __shared__ int s_i32, s_f32;
    const int tid = threadIdx.x;
    if (tid == 0) { s_i32 = 1; s_f32 = 1; }
    __syncthreads();
    {
        const unsigned* rw = (const unsigned*)reset_raw;
        int bad_i = 0, bad_f = 0;
        for (int q = tid; q < 4096; q += 256) {
            unsigned v = rw[q];
            if (v > 1u) bad_i = 1;
            if (v != 0u && v != 0x3F800000u) bad_f = 1;
        }
        if (bad_i) s_i32 = 0;
        if (bad_f) s_f32 = 0;
    }
    __syncthreads();
    const int rmode = s_i32 ? 0 : (s_f32 ? 1 : 2);
    const int*           r32 = (const int*)reset_raw;
    const float*         rf  = (const float*)reset_raw;
    const unsigned char* r8  = (const unsigned char*)reset_raw;

    for (int t = tid; t < TT; t += 256) {
        unsigned m = 0;
#pragma unroll
        for (int n = 0; n < NB; n++) {
            bool rv = (rmode == 0) ? (r32[n * TT + t] != 0)
                    : (rmode == 1) ? (rf[n * TT + t] != 0.f)
                                   : (r8[n * TT + t] != 0);
            m |= (unsigned)rv << n;
        }
        rbs[t] = m;
        g_rbits[t] = m;
        hist[t] = 0;
    }
    __syncthreads();
    if (tid < NB) {
        unsigned short d = 0;
        for (int t = 0; t < TT; t++) {
            if (t == 0 || ((rbs[t] >> tid) & 1u)) d = 0; else d++;
            depth[tid][t] = d;
            atomicAdd(&hist[d], 1u);
        }
    }
    __syncthreads();
    if (tid == 0) {
        unsigned acc = 0, maxd = 0;
        for (int w0 = 0; w0 < TT; w0++) {
            unsigned c = hist[w0];
            if (c) maxd = (unsigned)w0;
            curs[w0] = acc;
            g_waveoff[w0] = acc;
            acc += c;
        }
        g_waveoff[TT] = acc;
        g_nwaves = maxd + 1;
        g_bar = 0u;
    }
    __syncthreads();
    for (int p = tid; p < NPOS; p += 256) {
        int n = p >> 10, t = p & 1023;
        unsigned d = depth[n][t];
        unsigned slot = atomicAdd(&curs[d], 1u);
        g_poslist[slot] = (unsigned)p;
    }
    for (int q = tid; q < HH; q += 256)
        out[2 * (size_t)NTH_ELEMS + q] = initial_h[q];
}

// ---------------------------------------------------------------------------
__device__ __forceinline__ void grid_barrier(unsigned target) {
    __syncthreads();
    if (threadIdx.x == 0) {
        asm volatile("red.release.gpu.global.add.u32 [%0], 1;"
                     :: "l"(&g_bar) : "memory");
        unsigned v;
        do {
            asm volatile("ld.acquire.gpu.global.u32 %0, [%1];"
                         : "=r"(v) : "l"(&g_bar) : "memory");
        } while (v < target);
    }
    __syncthreads();
}

// ---------------------------------------------------------------------------
struct WaveCtx {
    const float* carry;
    const float* initial_h;
    const float* w_h;
    const float* bias;
    float* out;
    float* AsRaw;
    float (*Bs)[32][128];
    const unsigned* rbs;
    const float** rowp;
    unsigned* posv;
};

__device__ __forceinline__ void set_rows(const WaveCtx& C, int phase,
                                         int mtile, int POSB,
                                         unsigned base, unsigned cnt) {
    const int tid = threadIdx.x;
    __syncthreads();
    if (tid < POSB) {
        int idx = mtile * POSB + tid;
        unsigned pos = 0xFFFFFFFFu;
        const float* rp = C.initial_h;
        if ((unsigned)idx < cnt) {
            pos = g_poslist[base + idx];
            int n = pos >> 10, t = (int)(pos & 1023);
            if (phase)
                rp = g_rh + (size_t)pos * HH;
            else if ((C.rbs[t] >> n) & 1u)
                rp = C.initial_h;
            else if (t == 0)
                rp = C.carry + (size_t)n * TT * HH;
            else
                rp = C.out + (size_t)(pos - 1) * HH;
        }
        C.posv[tid] = pos;
        C.rowp[tid] = rp;
    }
    __syncthreads();
}

__device__ __forceinline__ void epi_seg(const WaveCtx& C, int phase,
                                        unsigned pos, int col0,
                                        const float* rowptr,
                                        u64 q0, u64 q1) {
    float2 f0 = unpk(q0), f1 = unpk(q1);
    float res[4] = {f0.x, f0.y, f1.x, f1.y};
    float4 gx0 = __ldcg((const float4*)(g_gx + (size_t)pos * G3 + col0));
    float gg[4] = {gx0.x, gx0.y, gx0.z, gx0.w};
    float4 bb0 = *(const float4*)(C.bias + col0);
    float bb[4] = {bb0.x, bb0.y, bb0.z, bb0.w};

    if (phase == 0 && col0 < HH) {
        float o[4];
#pragma unroll
        for (int s = 0; s < 4; s++) o[s] = sigm(gg[s] + res[s] + bb[s]);
        *(float4*)(g_z + (size_t)pos * HH + col0) =
            make_float4(o[0], o[1], o[2], o[3]);
    } else if (phase == 0) {
        const int j0 = col0 - HH;
        float4 h0 = __ldcg((const float4*)(rowptr + j0));
        float hh[4] = {h0.x, h0.y, h0.z, h0.w};
        float o[4];
#pragma unroll
        for (int s = 0; s < 4; s++)
            o[s] = sigm(gg[s] + res[s] + bb[s]) * hh[s];
        *(float4*)(g_rh + (size_t)pos * HH + j0) =
            make_float4(o[0], o[1], o[2], o[3]);
    } else {
        const int j0 = col0 - 2 * HH;
        int n = pos >> 10, t = (int)(pos & 1023);
        const float* hp = ((C.rbs[t] >> n) & 1u) ? C.initial_h
                        : (t == 0 ? C.carry + (size_t)n * TT * HH
                                  : C.out + (size_t)(pos - 1) * HH);
        float4 h0 = __ldcg((const float4*)(hp + j0));
        float hh[4] = {h0.x, h0.y, h0.z, h0.w};
        float4 z0 = __ldcg((const float4*)(g_z + (size_t)pos * HH + j0));
        float zz[4] = {z0.x, z0.y, z0.z, z0.w};
        float o[4];
#pragma unroll
        for (int s = 0; s < 4; s++) {
            float a = tanhf(gg[s] + res[s] + bb[s]);
            o[s] = (1.f - zz[s]) * hh[s] + zz[s] * a;
        }
        float* op = C.out + (size_t)pos * HH + j0;
        float4 v = make_float4(o[0], o[1], o[2], o[3]);
        *(float4*)op               = v;
        *(float4*)(op + NTH_ELEMS) = v;
    }
}

__device__ __forceinline__ void epilogue_row(const WaveCtx& C, int phase,
                                             int colbase, int tx,
                                             unsigned pos,
                                             const float* rowptr,
                                             const u64* accq) {
    epi_seg(C, phase, pos, colbase + tx * 4,      rowptr, accq[0], accq[1]);
    epi_seg(C, phase, pos, colbase + 64 + tx * 4, rowptr, accq[2], accq[3]);
}

// ---------------------------------------------------------------------------
#define AS8_STRIDE 132
__device__ void gemm_tile8(const WaveCtx& C, int phase, int mtile, int ntile,
                           unsigned base, unsigned cnt) {
    const int tid = threadIdx.x;
    const int tx = tid & 15;
    const int ty = tid >> 4;
    float* As8 = C.AsRaw;
    float (*Bs8)[16][128] = (float(*)[16][128])C.Bs;

    set_rows(C, phase, mtile, 128, base, cnt);

    const int colbase = (phase ? 2 * HH : 0) + ntile * 128;
    const float* wb = C.w_h + colbase;

    u64 acc[8][4];
#pragma unroll
    for (int r = 0; r < 8; r++)
#pragma unroll
        for (int j = 0; j < 4; j++) acc[r][j] = 0ull;

    float4 aL[2], bL[2];
    auto loadA = [&](int k0) {
#pragma unroll
        for (int p = 0; p < 2; p++) {
            int q = tid + 256 * p;
            int r = q >> 2, c4 = q & 3;
            aL[p] = __ldcg((const float4*)(C.rowp[r] + k0 + c4 * 4));
        }
    };
    auto storeA = [&](int buf) {
        float* bp = As8 + buf * 16 * AS8_STRIDE;
#pragma unroll
        for (int p = 0; p < 2; p++) {
            int q = tid + 256 * p;
            int r = q >> 2, c4 = q & 3;
            bp[(c4 * 4 + 0) * AS8_STRIDE + r] = aL[p].x;
            bp[(c4 * 4 + 1) * AS8_STRIDE + r] = aL[p].y;
            bp[(c4 * 4 + 2) * AS8_STRIDE + r] = aL[p].z;
            bp[(c4 * 4 + 3) * AS8_STRIDE + r] = aL[p].w;
        }
    };
    auto loadB = [&](int k0) {
#pragma unroll
        for (int p = 0; p < 2; p++) {
            int q = tid + 256 * p;
            int krow = q >> 5, col4 = q & 31;
            bL[p] = __ldcg((const float4*)(wb + (size_t)(k0 + krow) * G3 + col4 * 4));
        }
    };
    auto storeB = [&](int buf) {
#pragma unroll
        for (int p = 0; p < 2; p++) {
            int q = tid + 256 * p;
            int krow = q >> 5, col4 = q & 31;
            *(float4*)&Bs8[buf][krow][col4 * 4] = bL[p];
        }
    };

    loadA(0); loadB(0);
    storeA(0); storeB(0);
    for (int it = 0; it < 64; it++) {
        __syncthreads();
        const int db = it & 1;
        if (it < 63) { loadA((it + 1) * 16); loadB((it + 1) * 16); }
        const float* ab = As8 + db * 16 * AS8_STRIDE;
#pragma unroll
        for (int kk = 0; kk < 16; kk++) {
            float4 a0 = *(const float4*)(ab + kk * AS8_STRIDE + ty * 8);
            float4 a1 = *(const float4*)(ab + kk * AS8_STRIDE + ty * 8 + 4);
            ulonglong2 b01 = *(const ulonglong2*)&Bs8[db][kk][tx * 4];
            ulonglong2 b23 = *(const ulonglong2*)&Bs8[db][kk][64 + tx * 4];
            float av[8] = {a0.x, a0.y, a0.z, a0.w, a1.x, a1.y, a1.z, a1.w};
#pragma unroll
            for (int r = 0; r < 8; r++) {
                u64 ar = dup2(av[r]);
                fma2(acc[r][0], ar, b01.x);
                fma2(acc[r][1], ar, b01.y);
                fma2(acc[r][2], ar, b23.x);
                fma2(acc[r][3], ar, b23.y);
            }
        }
        if (it < 63) { const int nb = db ^ 1; storeA(nb); storeB(nb); }
    }

#pragma unroll
    for (int r = 0; r < 8; r++) {
        const int i = ty * 8 + r;
        unsigned pos = C.posv[i];
        if (pos == 0xFFFFFFFFu) continue;
        epilogue_row(C, phase, colbase, tx, pos, C.rowp[i], acc[r]);
    }
}

// ---------------------------------------------------------------------------
template<int R>
__device__ void gemm_tile(const WaveCtx& C, int phase, int mtile, int ntile,
                          unsigned base, unsigned cnt) {
    constexpr int POSB = R * 16;
    const int tid = threadIdx.x;
    const int tx = tid & 15;
    const int ty = tid >> 4;
    float (*As)[32][64] = (float(*)[32][64])C.AsRaw;

    set_rows(C, phase, mtile, POSB, base, cnt);

    const int colbase = (phase ? 2 * HH : 0) + ntile * 128;
    const float* wb = C.w_h + colbase;

    u64 acc[R][4];
#pragma unroll
    for (int r = 0; r < R; r++)
#pragma unroll
        for (int j = 0; j < 4; j++) acc[r][j] = 0ull;

    float4 aL[2], bL[4];
    auto loadA = [&](int k0) {
        if (R == 4) {
#pragma unroll
            for (int c = 0; c < 2; c++) {
                int q = tid + 256 * c;
                int i = q & 63, kc = q >> 6;
                aL[c] = __ldcg((const float4*)(C.rowp[i] + k0 + kc * 4));
            }
        } else {
            if (tid < 128) {
                int i = tid & 15, kc = tid >> 4;
                aL[0] = __ldcg((const float4*)(C.rowp[i] + k0 + kc * 4));
            }
        }
    };
    auto storeA = [&](int buf) {
        if (R == 4) {
#pragma unroll
            for (int c = 0; c < 2; c++) {
                int q = tid + 256 * c;
                int i = q & 63, kc = q >> 6;
                As[buf][kc * 4 + 0][i] = aL[c].x;
                As[buf][kc * 4 + 1][i] = aL[c].y;
                As[buf][kc * 4 + 2][i] = aL[c].z;
                As[buf][kc * 4 + 3][i] = aL[c].w;
            }
        } else {
            if (tid < 128) {
                int i = tid & 15, kc = tid >> 4;
                As[buf][kc * 4 + 0][i] = aL[0].x;
                As[buf][kc * 4 + 1][i] = aL[0].y;
                As[buf][kc * 4 + 2][i] = aL[0].z;
                As[buf][kc * 4 + 3][i] = aL[0].w;
            }
        }
    };
    auto loadB = [&](int k0) {
#pragma unroll
        for (int c = 0; c < 4; c++) {
            int q = tid + 256 * c;
            int row = q >> 5, c4 = q & 31;
            bL[c] = __ldcg((const float4*)(wb + (size_t)(k0 + row) * G3 + c4 * 4));
        }
    };
    auto storeB = [&](int buf) {
#pragma unroll
        for (int c = 0; c < 4; c++) {
            int q = tid + 256 * c;
            int row = q >> 5, c4 = q & 31;
            *(float4*)&C.Bs[buf][row][c4 * 4] = bL[c];
        }
    };

    loadA(0); loadB(0);
    storeA(0); storeB(0);
    for (int it = 0; it < 32; it++) {
        __syncthreads();
        const int db = it & 1;
        if (it < 31) { loadA((it + 1) * 32); loadB((it + 1) * 32); }
#pragma unroll
        for (int kk = 0; kk < 32; kk++) {
            float av[R];
            if (R == 4) {
                float4 a4 = *(const float4*)&As[db][kk][ty * 4];
                av[0] = a4.x; av[1] = a4.y; av[2] = a4.z; av[3] = a4.w;
            } else {
                av[0] = As[db][kk][ty];
            }
            ulonglong2 b01 = *(const ulonglong2*)&C.Bs[db][kk][tx * 4];
            ulonglong2 b23 = *(const ulonglong2*)&C.Bs[db][kk][64 + tx * 4];
#pragma unroll
            for (int r = 0; r < R; r++) {
                u64 ar = dup2(av[r]);
                fma2(acc[r][0], ar, b01.x);
                fma2(acc[r][1], ar, b01.y);
                fma2(acc[r][2], ar, b23.x);
                fma2(acc[r][3], ar, b23.y);
            }
        }
        if (it < 31) { const int nb = db ^ 1; storeA(nb); storeB(nb); }
    }

#pragma unroll
    for (int r = 0; r < R; r++) {
        const int i = ty * R + r;
        unsigned pos = C.posv[i];
        if (pos == 0xFFFFFFFFu) continue;
        epilogue_row(C, phase, colbase, tx, pos, C.rowp[i], acc[r]);
    }
}

// ---------------------------------------------------------------------------
__global__ void __launch_bounds__(WTHR, 2) wave_kernel(
        const float* __restrict__ carry,
        const float* __restrict__ initial_h,
        const float* __restrict__ w_h,
        const float* __restrict__ bias,
        float* __restrict__ out) {
    extern __shared__ char smw[];
    WaveCtx C;
    C.AsRaw = (float*)smw;                              // 16896 B
    C.Bs    = (float(*)[32][128])(smw + 16896);         // 32768 B
    unsigned* rbs = (unsigned*)(smw + 49664);           //  4096 B
    C.rowp  = (const float**)(smw + 53760);             //  1024 B
    C.posv  = (unsigned*)(smw + 54784);                 //   512 B
    C.rbs = rbs;
    C.carry = carry; C.initial_h = initial_h;
    C.w_h = w_h; C.bias = bias; C.out = out;

    const int tid = threadIdx.x;
    for (int t = tid; t < TT; t += WTHR) rbs[t] = g_rbits[t];
    __syncthreads();

    const unsigned nw = g_nwaves;
    unsigned bar_t = 0;

    for (unsigned wv = 0; wv < nw; wv++) {
        const unsigned base = g_waveoff[wv];
        const unsigned cnt  = g_waveoff[wv + 1] - base;
        const int kind = (cnt >= 1536) ? 2 : (cnt >= 256 ? 1 : 0);
        const int mt = (kind == 2) ? (int)((cnt + 127) >> 7)
                     : (kind == 1) ? (int)((cnt + 63) >> 6)
                                   : (int)((cnt + 15) >> 4);

        for (int tile = blockIdx.x; tile < mt * 16; tile += NCTA_W) {
            if (kind == 2)      gemm_tile8(C, 0, tile >> 4, tile & 15, base, cnt);
            else if (kind == 1) gemm_tile<4>(C, 0, tile >> 4, tile & 15, base, cnt);
            else                gemm_tile<1>(C, 0, tile >> 4, tile & 15, base, cnt);
        }
        bar_t += NCTA_W;
        grid_barrier(bar_t);

        for (int tile = blockIdx.x; tile < mt * 8; tile += NCTA_W) {
            if (kind == 2)      gemm_tile8(C, 1, tile >> 3, tile & 7, base, cnt);
            else if (kind == 1) gemm_tile<4>(C, 1, tile >> 3, tile & 7, base, cnt);
            else                gemm_tile<1>(C, 1, tile >> 3, tile & 7, base, cnt);
        }
        bar_t += NCTA_W;
        grid_barrier(bar_t);
    }
}

// ---------------------------------------------------------------------------
extern "C" void kernel_launch(void* const* d_in, const int* in_sizes, int n_in,
                              void* d_out, int out_size) {
    const float* x         = (const float*)d_in[0];
    const void*  reset     = d_in[1];
    const float* carry     = (const float*)d_in[2];
    const float* initial_h = (const float*)d_in[3];
    const float* w_i       = (const float*)d_in[4];
    const float* w_h       = (const float*)d_in[5];
    const float* b         = (const float*)d_in[6];
    float*       out       = (float*)d_out;
    (void)in_sizes; (void)n_in; (void)out_size;

    prep_kernel<<<2048, 256>>>(x, w_i);

    cudaFuncSetAttribute((const void*)gx_mma_kernel,
                         cudaFuncAttributeMaxDynamicSharedMemorySize, GX_SMEM);
    dim3 tgrid(G3 / 128, NPOS / 128);
    gx_mma_kernel<<<tgrid, 256, GX_SMEM>>>();

    setup_kernel<<<1, 256>>>(reset, initial_h, out);

    size_t smem = 55296;
    cudaFuncSetAttribute((const void*)wave_kernel,
                         cudaFuncAttributeMaxDynamicSharedMemorySize, (int)smem);
    wave_kernel<<<NCTA_W, WTHR, smem>>>(carry, initial_h, w_h, b, out);
}

// round 13
// speedup vs baseline: 1.5282x; 1.2663x over previous
#include <cuda_runtime.h>
#include <cuda_bf16.h>

#define NB 16
#define TT 1024
#define HH 1024
#define G3 3072
#define NPOS (NB*TT)
#define NTH_ELEMS (NB*TT*HH)
#define NCTA_W 296
#define WTHR 256

typedef unsigned long long u64;

// scratch
__device__ float          g_gx[(size_t)NPOS * G3];   // 192 MB, position-ordered
__device__ float          g_rh[(size_t)NPOS * HH];
__device__ float          g_z [(size_t)NPOS * HH];
__device__ __nv_bfloat16  g_xh[(size_t)NPOS * HH];
__device__ __nv_bfloat16  g_xl[(size_t)NPOS * HH];
__device__ __nv_bfloat16  g_wth[(size_t)G3 * HH];    // w_i^T hi
__device__ __nv_bfloat16  g_wtl[(size_t)G3 * HH];    // w_i^T lo
__device__ __nv_bfloat16  g_whh[(size_t)G3 * HH];    // w_h^T hi
__device__ __nv_bfloat16  g_whl[(size_t)G3 * HH];    // w_h^T lo
__device__ unsigned g_rbits[TT];
__device__ unsigned g_poslist[NPOS];
__device__ unsigned g_waveoff[TT + 1];
__device__ unsigned g_nwaves;
__device__ unsigned g_bar;

// ---- packed fp32x2 helpers ----
__device__ __forceinline__ void fma2(u64& d, u64 a, u64 b) {
    asm("fma.rn.f32x2 %0, %1, %2, %0;" : "+l"(d) : "l"(a), "l"(b));
}
__device__ __forceinline__ u64 dup2(float x) {
    u64 r; asm("mov.b64 %0, {%1, %1};" : "=l"(r) : "f"(x)); return r;
}
__device__ __forceinline__ float2 unpk(u64 v) {
    float2 r; asm("mov.b64 {%0, %1}, %2;" : "=f"(r.x), "=f"(r.y) : "l"(v)); return r;
}
__device__ __forceinline__ float sigm(float x) {
    return 1.f / (1.f + __expf(-x));
}
__device__ __forceinline__ unsigned su32(const void* p) {
    unsigned a;
    asm("{ .reg .u64 t; cvta.to.shared.u64 t, %1; cvt.u32.u64 %0, t; }"
        : "=r"(a) : "l"(p));
    return a;
}

// ---- mma.sync helpers (baseline ISA) ----
__device__ __forceinline__ void ldm_x4(unsigned addr, unsigned r[4]) {
    asm volatile("ldmatrix.sync.aligned.m8n8.x4.shared.b16 {%0,%1,%2,%3}, [%4];"
        : "=r"(r[0]), "=r"(r[1]), "=r"(r[2]), "=r"(r[3]) : "r"(addr));
}
__device__ __forceinline__ void mma16816(float d[4], const unsigned a[4],
                                         unsigned b0, unsigned b1) {
    asm volatile(
        "mma.sync.aligned.m16n8k16.row.col.f32.bf16.bf16.f32 "
        "{%0,%1,%2,%3}, {%4,%5,%6,%7}, {%8,%9}, {%0,%1,%2,%3};"
        : "+f"(d[0]), "+f"(d[1]), "+f"(d[2]), "+f"(d[3])
        : "r"(a[0]), "r"(a[1]), "r"(a[2]), "r"(a[3]), "r"(b0), "r"(b1));
}

// ---------------------------------------------------------------------------
// prep: bf16 hi/lo splits of x, w_i^T, w_h^T
// ---------------------------------------------------------------------------
__global__ void prep_kernel(const float* __restrict__ x,
                            const float* __restrict__ w_i,
                            const float* __restrict__ w_h) {
    const size_t stride = (size_t)gridDim.x * blockDim.x;
    size_t i0 = (size_t)blockIdx.x * blockDim.x + threadIdx.x;
    for (size_t i = i0; i < (size_t)NPOS * HH; i += stride) {
        float v = x[i];
        __nv_bfloat16 h = __float2bfloat16(v);
        g_xh[i] = h;
        g_xl[i] = __float2bfloat16(v - __bfloat162float(h));
    }
    for (size_t i = i0; i < (size_t)G3 * HH; i += stride) {
        size_t k = i / G3, n = i % G3;
        float v = w_i[i];
        __nv_bfloat16 h = __float2bfloat16(v);
        g_wth[n * HH + k] = h;
        g_wtl[n * HH + k] = __float2bfloat16(v - __bfloat162float(h));
        float vh = w_h[i];
        __nv_bfloat16 hh = __float2bfloat16(vh);
        g_whh[n * HH + k] = hh;
        g_whl[n * HH + k] = __float2bfloat16(vh - __bfloat162float(hh));
    }
}

// ---------------------------------------------------------------------------
// gx via mma.sync bf16x3 (unchanged from R12)
// ---------------------------------------------------------------------------
#define STRD 40
#define GX_SMEM 81920

__global__ void __launch_bounds__(256, 1) gx_mma_kernel() {
    extern __shared__ __nv_bfloat16 sb[];
    const int tid = threadIdx.x;
    const int lane = tid & 31;
    const int wid = tid >> 5;
    const int wm = wid >> 1;
    const int wn = wid & 1;
    const int m0 = blockIdx.y * 128;
    const int n0 = blockIdx.x * 128;

    __nv_bfloat16* Ah = sb;
    __nv_bfloat16* Al = sb + 10240;
    __nv_bfloat16* Bh = sb + 20480;
    __nv_bfloat16* Bl = sb + 30720;
    const unsigned aAh = su32(Ah);
    const unsigned aBh = su32(Bh);

    float d[2][8][4];
#pragma unroll
    for (int mt = 0; mt < 2; mt++)
#pragma unroll
        for (int nt = 0; nt < 8; nt++)
#pragma unroll
            for (int j = 0; j < 4; j++) d[mt][nt][j] = 0.f;

    const unsigned aoff = (unsigned)(((lane & 15) * STRD + (lane >> 4) * 8) * 2);
    const unsigned boff = (unsigned)(((((lane & 7) + ((lane >> 4) << 3)) * STRD) +
                                     (((lane >> 3) & 1) * 8)) * 2);

    uint4 rah[2], ral[2], rbh[2], rbl[2];
    auto loadAB = [&](int kc0) {
#pragma unroll
        for (int p = 0; p < 2; p++) {
            int q = tid + 256 * p;
            int r = q >> 2, sg = q & 3;
            size_t offa = (size_t)(m0 + r) * HH + kc0 + sg * 8;
            size_t offb = (size_t)(n0 + r) * HH + kc0 + sg * 8;
            rah[p] = *(const uint4*)(g_xh + offa);
            ral[p] = *(const uint4*)(g_xl + offa);
            rbh[p] = *(const uint4*)(g_wth + offb);
            rbl[p] = *(const uint4*)(g_wtl + offb);
        }
    };
    auto storeAB = [&](int buf) {
#pragma unroll
        for (int p = 0; p < 2; p++) {
            int q = tid + 256 * p;
            int r = q >> 2, sg = q & 3;
            int so = buf * 5120 + r * STRD + sg * 8;
            *(uint4*)(Ah + so) = rah[p];
            *(uint4*)(Al + so) = ral[p];
            *(uint4*)(Bh + so) = rbh[p];
            *(uint4*)(Bl + so) = rbl[p];
        }
    };

    loadAB(0);
    storeAB(0);

    for (int ch = 0; ch < 32; ch++) {
        __syncthreads();
        const int db = ch & 1;
        if (ch < 31) loadAB((ch + 1) * 32);

#pragma unroll
        for (int ks = 0; ks < 2; ks++) {
            unsigned ah[2][4], al[2][4];
#pragma unroll
            for (int mt = 0; mt < 2; mt++) {
                unsigned base = aAh + (unsigned)(db * 10240 +
                                (wm * 32 + mt * 16) * 80 + ks * 32) + aoff;
                ldm_x4(base, ah[mt]);
                ldm_x4(base + 20480u, al[mt]);
            }
#pragma unroll
            for (int bt = 0; bt < 4; bt++) {
                unsigned bh[4], bl[4];
                unsigned baseb = aBh + (unsigned)(db * 10240 +
                                 (wn * 64 + bt * 16) * 80 + ks * 32) + boff;
                ldm_x4(baseb, bh);
                ldm_x4(baseb + 20480u, bl);
#pragma unroll
                for (int mt = 0; mt < 2; mt++) {
                    mma16816(d[mt][bt * 2],     ah[mt], bh[0], bh[1]);
                    mma16816(d[mt][bt * 2],     ah[mt], bl[0], bl[1]);
                    mma16816(d[mt][bt * 2],     al[mt], bh[0], bh[1]);
                    mma16816(d[mt][bt * 2 + 1], ah[mt], bh[2], bh[3]);
                    mma16816(d[mt][bt * 2 + 1], ah[mt], bl[2], bl[3]);
                    mma16816(d[mt][bt * 2 + 1], al[mt], bh[2], bh[3]);
                }
            }
        }
        if (ch < 31) storeAB(db ^ 1);
    }

#pragma unroll
    for (int mt = 0; mt < 2; mt++) {
        int row = m0 + wm * 32 + mt * 16 + (lane >> 2);
#pragma unroll
        for (int nt = 0; nt < 8; nt++) {
            int col = n0 + wn * 64 + nt * 8 + (lane & 3) * 2;
            float* p0 = g_gx + (size_t)row * G3 + col;
            *(float2*)p0            = make_float2(d[mt][nt][0], d[mt][nt][1]);
            *(float2*)(p0 + 8 * G3) = make_float2(d[mt][nt][2], d[mt][nt][3]);
        }
    }
}

// ---------------------------------------------------------------------------
// setup (unchanged)
// ---------------------------------------------------------------------------
__global__ void setup_kernel(const void* __restrict__ reset_raw,
                             const float* __restrict__ initial_h,
                             float* __restrict__ out) {
    __shared__ unsigned hist[TT];
    __shared__ unsigned curs[TT];
    __shared__ unsigned rbs[TT];
    __shared__ unsigned short depth[NB][TT];
    __shared__ int s_i32, s_f32;
    const int tid = threadIdx.x;
    if (tid == 0) { s_i32 = 1; s_f32 = 1; }
    __syncthreads();
    {
        const unsigned* rw = (const unsigned*)reset_raw;
        int bad_i = 0, bad_f = 0;
        for (int q = tid; q < 4096; q += 256) {
            unsigned v = rw[q];
            if (v > 1u) bad_i = 1;
            if (v != 0u && v != 0x3F800000u) bad_f = 1;
        }
        if (bad_i) s_i32 = 0;
        if (bad_f) s_f32 = 0;
    }
    __syncthreads();
    const int rmode = s_i32 ? 0 : (s_f32 ? 1 : 2);
    const int*           r32 = (const int*)reset_raw;
    const float*         rf  = (const float*)reset_raw;
    const unsigned char* r8  = (const unsigned char*)reset_raw;

    for (int t = tid; t < TT; t += 256) {
        unsigned m = 0;
#pragma unroll
        for (int n = 0; n < NB; n++) {
            bool rv = (rmode == 0) ? (r32[n * TT + t] != 0)
                    : (rmode == 1) ? (rf[n * TT + t] != 0.f)
                                   : (r8[n * TT + t] != 0);
            m |= (unsigned)rv << n;
        }
        rbs[t] = m;
        g_rbits[t] = m;
        hist[t] = 0;
    }
    __syncthreads();
    if (tid < NB) {
        unsigned short d = 0;
        for (int t = 0; t < TT; t++) {
            if (t == 0 || ((rbs[t] >> tid) & 1u)) d = 0; else d++;
            depth[tid][t] = d;
            atomicAdd(&hist[d], 1u);
        }
    }
    __syncthreads();
    if (tid == 0) {
        unsigned acc = 0, maxd = 0;
        for (int w0 = 0; w0 < TT; w0++) {
            unsigned c = hist[w0];
            if (c) maxd = (unsigned)w0;
            curs[w0] = acc;
            g_waveoff[w0] = acc;
            acc += c;
        }
        g_waveoff[TT] = acc;
        g_nwaves = maxd + 1;
        g_bar = 0u;
    }
    __syncthreads();
    for (int p = tid; p < NPOS; p += 256) {
        int n = p >> 10, t = p & 1023;
        unsigned d = depth[n][t];
        unsigned slot = atomicAdd(&curs[d], 1u);
        g_poslist[slot] = (unsigned)p;
    }
    for (int q = tid; q < HH; q += 256)
        out[2 * (size_t)NTH_ELEMS + q] = initial_h[q];
}

// ---------------------------------------------------------------------------
__device__ __forceinline__ void grid_barrier(unsigned target) {
    __syncthreads();
    if (threadIdx.x == 0) {
        asm volatile("red.release.gpu.global.add.u32 [%0], 1;"
                     :: "l"(&g_bar) : "memory");
        unsigned v;
        do {
            asm volatile("ld.acquire.gpu.global.u32 %0, [%1];"
                         : "=r"(v) : "l"(&g_bar) : "memory");
        } while (v < target);
    }
    __syncthreads();
}

// ---------------------------------------------------------------------------
struct WaveCtx {
    const float* carry;
    const float* initial_h;
    const float* w_h;
    const float* bias;
    float* out;
    float* AsRaw;                 // union: MMA bf16 regions / FFMA2 As+Bs
    float (*Bs)[32][128];
    const unsigned* rbs;
    const float** rowp;
    unsigned* posv;
};

__device__ __forceinline__ void set_rows(const WaveCtx& C, int phase,
                                         int mtile, int POSB,
                                         unsigned base, unsigned cnt) {
    const int tid = threadIdx.x;
    __syncthreads();
    if (tid < POSB) {
        int idx = mtile * POSB + tid;
        unsigned pos = 0xFFFFFFFFu;
        const float* rp = C.initial_h;
        if ((unsigned)idx < cnt) {
            pos = g_poslist[base + idx];
            int n = pos >> 10, t = (int)(pos & 1023);
            if (phase)
                rp = g_rh + (size_t)pos * HH;
            else if ((C.rbs[t] >> n) & 1u)
                rp = C.initial_h;
            else if (t == 0)
                rp = C.carry + (size_t)n * TT * HH;
            else
                rp = C.out + (size_t)(pos - 1) * HH;
        }
        C.posv[tid] = pos;
        C.rowp[tid] = rp;
    }
    __syncthreads();
}

// ---- epilogue: 2-column pair (for MMA tiles) ----
__device__ __forceinline__ void epi_pair(const WaveCtx& C, int phase,
                                         unsigned pos, int col0,
                                         const float* rowptr,
                                         float res0, float res1) {
    float2 gx = __ldcg((const float2*)(g_gx + (size_t)pos * G3 + col0));
    float2 bb = *(const float2*)(C.bias + col0);
    if (phase == 0 && col0 < HH) {
        float z0 = sigm(gx.x + res0 + bb.x);
        float z1 = sigm(gx.y + res1 + bb.y);
        *(float2*)(g_z + (size_t)pos * HH + col0) = make_float2(z0, z1);
    } else if (phase == 0) {
        const int j0 = col0 - HH;
        float2 h = __ldcg((const float2*)(rowptr + j0));
        float r0 = sigm(gx.x + res0 + bb.x);
        float r1 = sigm(gx.y + res1 + bb.y);
        *(float2*)(g_rh + (size_t)pos * HH + j0) =
            make_float2(r0 * h.x, r1 * h.y);
    } else {
        const int j0 = col0 - 2 * HH;
        int n = pos >> 10, t = (int)(pos & 1023);
        const float* hp = ((C.rbs[t] >> n) & 1u) ? C.initial_h
                        : (t == 0 ? C.carry + (size_t)n * TT * HH
                                  : C.out + (size_t)(pos - 1) * HH);
        float2 h = __ldcg((const float2*)(hp + j0));
        float2 z = __ldcg((const float2*)(g_z + (size_t)pos * HH + j0));
        float a0 = tanhf(gx.x + res0 + bb.x);
        float a1 = tanhf(gx.y + res1 + bb.y);
        float o0 = (1.f - z.x) * h.x + z.x * a0;
        float o1 = (1.f - z.y) * h.y + z.y * a1;
        float* op = C.out + (size_t)pos * HH + j0;
        *(float2*)op               = make_float2(o0, o1);
        *(float2*)(op + NTH_ELEMS) = make_float2(o0, o1);
    }
}

// ---- epilogue: 4-column segment (for FFMA2 tiles) ----
__device__ __forceinline__ void epi_seg(const WaveCtx& C, int phase,
                                        unsigned pos, int col0,
                                        const float* rowptr,
                                        u64 q0, u64 q1) {
    float2 f0 = unpk(q0), f1 = unpk(q1);
    epi_pair(C, phase, pos, col0,     rowptr, f0.x, f0.y);
    epi_pair(C, phase, pos, col0 + 2, rowptr, f1.x, f1.y);
}

__device__ __forceinline__ void epilogue_row(const WaveCtx& C, int phase,
                                             int colbase, int tx,
                                             unsigned pos,
                                             const float* rowptr,
                                             const u64* accq) {
    epi_seg(C, phase, pos, colbase + tx * 4,      rowptr, accq[0], accq[1]);
    epi_seg(C, phase, pos, colbase + 64 + tx * 4, rowptr, accq[2], accq[3]);
}

// ---------------------------------------------------------------------------
// big tile via mma.sync bf16x3: 128 gathered rows x 128 cols, K=1024
// smem: Ah/Al/Bh/Bl each [2][128][24] bf16; K-chunk 16, double-buffered
// ---------------------------------------------------------------------------
#define MSTRD 24
__device__ void gemm_tile8_mma(const WaveCtx& C, int phase, int mtile, int ntile,
                               unsigned base, unsigned cnt) {
    const int tid = threadIdx.x;
    const int lane = tid & 31;
    const int wid = tid >> 5;
    const int wm = wid >> 1;      // 0..3
    const int wn = wid & 1;       // 0..1

    set_rows(C, phase, mtile, 128, base, cnt);

    const int colbase = (phase ? 2 * HH : 0) + ntile * 128;

    __nv_bfloat16* Ah = (__nv_bfloat16*)C.AsRaw;   // [2][128][24]
    const unsigned aAh = su32(Ah);
    // region offsets in bytes: Al=+12288, Bh=+24576, Bl=+36864 (each 6144 elem)

    float d[2][8][4];
#pragma unroll
    for (int mt = 0; mt < 2; mt++)
#pragma unroll
        for (int nt = 0; nt < 8; nt++)
#pragma unroll
            for (int j = 0; j < 4; j++) d[mt][nt][j] = 0.f;

    const unsigned aoff = (unsigned)((lane & 15) * (MSTRD * 2) + (lane >> 4) * 16);
    const unsigned boff = (unsigned)((((lane & 7) + ((lane >> 4) << 3)) * (MSTRD * 2)) +
                                     (((lane >> 3) & 1) * 16));

    const int r  = tid >> 1;       // row 0..127
    const int sg = tid & 1;        // 8-col segment
    const __nv_bfloat16* bsrc_h = g_whh + (size_t)(colbase + r) * HH + sg * 8;
    const __nv_bfloat16* bsrc_l = g_whl + (size_t)(colbase + r) * HH + sg * 8;

    float4 fa0, fa1;
    uint4 rbh, rbl;
    auto loadChunk = [&](int k0) {
        fa0 = __ldcg((const float4*)(C.rowp[r] + k0 + sg * 8));
        fa1 = __ldcg((const float4*)(C.rowp[r] + k0 + sg * 8 + 4));
        rbh = __ldcg((const uint4*)(bsrc_h + k0));
        rbl = __ldcg((const uint4*)(bsrc_l + k0));
    };
    auto storeChunk = [&](int buf) {
        float fa[8] = {fa0.x, fa0.y, fa0.z, fa0.w, fa1.x, fa1.y, fa1.z, fa1.w};
        __align__(16) __nv_bfloat16 hh[8], ll[8];
#pragma unroll
        for (int s = 0; s < 8; s++) {
            __nv_bfloat16 h = __float2bfloat16(fa[s]);
            hh[s] = h;
            ll[s] = __float2bfloat16(fa[s] - __bfloat162float(h));
        }
        int so = buf * 3072 + r * MSTRD + sg * 8;
        *(uint4*)(Ah + so)         = *(const uint4*)hh;
        *(uint4*)(Ah + 6144 + so)  = *(const uint4*)ll;
        *(uint4*)(Ah + 12288 + so) = rbh;
        *(uint4*)(Ah + 18432 + so) = rbl;
    };

    loadChunk(0);
    storeChunk(0);

    for (int ch = 0; ch < 64; ch++) {
        __syncthreads();
        const int db = ch & 1;
        if (ch < 63) loadChunk((ch + 1) * 16);

        unsigned ah[2][4], al[2][4];
#pragma unroll
        for (int mt = 0; mt < 2; mt++) {
            unsigned ba = aAh + (unsigned)(db * 6144 +
                          (wm * 32 + mt * 16) * (MSTRD * 2)) + aoff;
            ldm_x4(ba, ah[mt]);
            ldm_x4(ba + 12288u, al[mt]);
        }
#pragma unroll
        for (int bt = 0; bt < 4; bt++) {
            unsigned bh4[4], bl4[4];
            unsigned bb = aAh + 24576u + (unsigned)(db * 6144 +
                          (wn * 64 + bt * 16) * (MSTRD * 2)) + boff;
            ldm_x4(bb, bh4);
            ldm_x4(bb + 12288u, bl4);
#pragma unroll
            for (int mt = 0; mt < 2; mt++) {
                mma16816(d[mt][bt * 2],     ah[mt], bh4[0], bh4[1]);
                mma16816(d[mt][bt * 2],     ah[mt], bl4[0], bl4[1]);
                mma16816(d[mt][bt * 2],     al[mt], bh4[0], bh4[1]);
                mma16816(d[mt][bt * 2 + 1], ah[mt], bh4[2], bh4[3]);
                mma16816(d[mt][bt * 2 + 1], ah[mt], bl4[2], bl4[3]);
                mma16816(d[mt][bt * 2 + 1], al[mt], bh4[2], bh4[3]);
            }
        }
        if (ch < 63) storeChunk(db ^ 1);
    }

    // epilogue
#pragma unroll
    for (int mt = 0; mt < 2; mt++) {
#pragma unroll
        for (int half = 0; half < 2; half++) {
            const int i = wm * 32 + mt * 16 + (lane >> 2) + half * 8;
            unsigned pos = C.posv[i];
            if (pos == 0xFFFFFFFFu) continue;
            const float* rp = C.rowp[i];
#pragma unroll
            for (int nt = 0; nt < 8; nt++) {
                int col = colbase + wn * 64 + nt * 8 + (lane & 3) * 2;
                epi_pair(C, phase, pos, col, rp,
                         d[mt][nt][half * 2], d[mt][nt][half * 2 + 1]);
            }
        }
    }
}

// ---------------------------------------------------------------------------
// medium/small tile: FFMA2 (unchanged)
// ---------------------------------------------------------------------------
template<int R>
__device__ void gemm_tile(const WaveCtx& C, int phase, int mtile, int ntile,
                          unsigned base, unsigned cnt) {
    constexpr int POSB = R * 16;
    const int tid = threadIdx.x;
    const int tx = tid & 15;
    const int ty = tid >> 4;
    float (*As)[32][64] = (float(*)[32][64])C.AsRaw;

    set_rows(C, phase, mtile, POSB, base, cnt);

    const int colbase = (phase ? 2 * HH : 0) + ntile * 128;
    const float* wb = C.w_h + colbase;

    u64 acc[R][4];
#pragma unroll
    for (int r = 0; r < R; r++)
#pragma unroll
        for (int j = 0; j < 4; j++) acc[r][j] = 0ull;

    float4 aL[2], bL[4];
    auto loadA = [&](int k0) {
        if (R == 4) {
#pragma unroll
            for (int c = 0; c < 2; c++) {
                int q = tid + 256 * c;
                int i = q & 63, kc = q >> 6;
                aL[c] = __ldcg((const float4*)(C.rowp[i] + k0 + kc * 4));
            }
        } else {
            if (tid < 128) {
                int i = tid & 15, kc = tid >> 4;
                aL[0] = __ldcg((const float4*)(C.rowp[i] + k0 + kc * 4));
            }
        }
    };
    auto storeA = [&](int buf) {
        if (R == 4) {
#pragma unroll
            for (int c = 0; c < 2; c++) {
                int q = tid + 256 * c;
                int i = q & 63, kc = q >> 6;
                As[buf][kc * 4 + 0][i] = aL[c].x;
                As[buf][kc * 4 + 1][i] = aL[c].y;
                As[buf][kc * 4 + 2][i] = aL[c].z;
                As[buf][kc * 4 + 3][i] = aL[c].w;
            }
        } else {
            if (tid < 128) {
                int i = tid & 15, kc = tid >> 4;
                As[buf][kc * 4 + 0][i] = aL[0].x;
                As[buf][kc * 4 + 1][i] = aL[0].y;
                As[buf][kc * 4 + 2][i] = aL[0].z;
                As[buf][kc * 4 + 3][i] = aL[0].w;
            }
        }
    };
    auto loadB = [&](int k0) {
#pragma unroll
        for (int c = 0; c < 4; c++) {
            int q = tid + 256 * c;
            int row = q >> 5, c4 = q & 31;
            bL[c] = __ldcg((const float4*)(wb + (size_t)(k0 + row) * G3 + c4 * 4));
        }
    };
    auto storeB = [&](int buf) {
#pragma unroll
        for (int c = 0; c < 4; c++) {
            int q = tid + 256 * c;
            int row = q >> 5, c4 = q & 31;
            *(float4*)&C.Bs[buf][row][c4 * 4] = bL[c];
        }
    };

    loadA(0); loadB(0);
    storeA(0); storeB(0);
    for (int it = 0; it < 32; it++) {
        __syncthreads();
        const int db = it & 1;
        if (it < 31) { loadA((it + 1) * 32); loadB((it + 1) * 32); }
#pragma unroll
        for (int kk = 0; kk < 32; kk++) {
            float av[R];
            if (R == 4) {
                float4 a4 = *(const float4*)&As[db][kk][ty * 4];
                av[0] = a4.x; av[1] = a4.y; av[2] = a4.z; av[3] = a4.w;
            } else {
                av[0] = As[db][kk][ty];
            }
            ulonglong2 b01 = *(const ulonglong2*)&C.Bs[db][kk][tx * 4];
            ulonglong2 b23 = *(const ulonglong2*)&C.Bs[db][kk][64 + tx * 4];
#pragma unroll
            for (int r = 0; r < R; r++) {
                u64 ar = dup2(av[r]);
                fma2(acc[r][0], ar, b01.x);
                fma2(acc[r][1], ar, b01.y);
                fma2(acc[r][2], ar, b23.x);
                fma2(acc[r][3], ar, b23.y);
            }
        }
        if (it < 31) { const int nb = db ^ 1; storeA(nb); storeB(nb); }
    }

#pragma unroll
    for (int r = 0; r < R; r++) {
        const int i = ty * R + r;
        unsigned pos = C.posv[i];
        if (pos == 0xFFFFFFFFu) continue;
        epilogue_row(C, phase, colbase, tx, pos, C.rowp[i], acc[r]);
    }
}

// ---------------------------------------------------------------------------
__global__ void __launch_bounds__(WTHR, 2) wave_kernel(
        const float* __restrict__ carry,
        const float* __restrict__ initial_h,
        const float* __restrict__ w_h,
        const float* __restrict__ bias,
        float* __restrict__ out) {
    extern __shared__ char smw[];
    WaveCtx C;
    C.AsRaw = (float*)smw;                              // union region 49664 B
    C.Bs    = (float(*)[32][128])(smw + 16896);
    unsigned* rbs = (unsigned*)(smw + 49664);           //  4096 B
    C.rowp  = (const float**)(smw + 53760);             //  1024 B
    C.posv  = (unsigned*)(smw + 54784);                 //   512 B
    C.rbs = rbs;
    C.carry = carry; C.initial_h = initial_h;
    C.w_h = w_h; C.bias = bias; C.out = out;

    const int tid = threadIdx.x;
    for (int t = tid; t < TT; t += WTHR) rbs[t] = g_rbits[t];
    __syncthreads();

    const unsigned nw = g_nwaves;
    unsigned bar_t = 0;

    for (unsigned wv = 0; wv < nw; wv++) {
        const unsigned base = g_waveoff[wv];
        const unsigned cnt  = g_waveoff[wv + 1] - base;
        const int kind = (cnt >= 1536) ? 2 : (cnt >= 256 ? 1 : 0);
        const int mt = (kind == 2) ? (int)((cnt + 127) >> 7)
                     : (kind == 1) ? (int)((cnt + 63) >> 6)
                                   : (int)((cnt + 15) >> 4);

        for (int tile = blockIdx.x; tile < mt * 16; tile += NCTA_W) {
            if (kind == 2)      gemm_tile8_mma(C, 0, tile >> 4, tile & 15, base, cnt);
            else if (kind == 1) gemm_tile<4>(C, 0, tile >> 4, tile & 15, base, cnt);
            else                gemm_tile<1>(C, 0, tile >> 4, tile & 15, base, cnt);
        }
        bar_t += NCTA_W;
        grid_barrier(bar_t);

        for (int tile = blockIdx.x; tile < mt * 8; tile += NCTA_W) {
            if (kind == 2)      gemm_tile8_mma(C, 1, tile >> 3, tile & 7, base, cnt);
            else if (kind == 1) gemm_tile<4>(C, 1, tile >> 3, tile & 7, base, cnt);
            else                gemm_tile<1>(C, 1, tile >> 3, tile & 7, base, cnt);
        }
        bar_t += NCTA_W;
        grid_barrier(bar_t);
    }
}

// ---------------------------------------------------------------------------
extern "C" void kernel_launch(void* const* d_in, const int* in_sizes, int n_in,
                              void* d_out, int out_size) {
    const float* x         = (const float*)d_in[0];
    const void*  reset     = d_in[1];
    const float* carry     = (const float*)d_in[2];
    const float* initial_h = (const float*)d_in[3];
    const float* w_i       = (const float*)d_in[4];
    const float* w_h       = (const float*)d_in[5];
    const float* b         = (const float*)d_in[6];
    float*       out       = (float*)d_out;
    (void)in_sizes; (void)n_in; (void)out_size;

    prep_kernel<<<2048, 256>>>(x, w_i, w_h);

    cudaFuncSetAttribute((const void*)gx_mma_kernel,
                         cudaFuncAttributeMaxDynamicSharedMemorySize, GX_SMEM);
    dim3 tgrid(G3 / 128, NPOS / 128);
    gx_mma_kernel<<<tgrid, 256, GX_SMEM>>>();

    setup_kernel<<<1, 256>>>(reset, initial_h, out);

    size_t smem = 55296;
    cudaFuncSetAttribute((const void*)wave_kernel,
                         cudaFuncAttributeMaxDynamicSharedMemorySize, (int)smem);
    wave_kernel<<<NCTA_W, WTHR, smem>>>(carry, initial_h, w_h, b, out);
}

// round 14
// speedup vs baseline: 1.5339x; 1.0037x over previous
#include <cuda_runtime.h>
#include <cuda_bf16.h>

#define NB 16
#define TT 1024
#define HH 1024
#define G3 3072
#define NPOS (NB*TT)
#define NTH_ELEMS (NB*TT*HH)
#define NCTA_W 296
#define WTHR 256

typedef unsigned long long u64;

// scratch
__device__ float          g_gx[(size_t)NPOS * G3];
__device__ float          g_rh[(size_t)NPOS * HH];
__device__ float          g_z [(size_t)NPOS * HH];
__device__ __nv_bfloat16  g_xh[(size_t)NPOS * HH];
__device__ __nv_bfloat16  g_xl[(size_t)NPOS * HH];
__device__ __nv_bfloat16  g_wth[(size_t)G3 * HH];
__device__ __nv_bfloat16  g_wtl[(size_t)G3 * HH];
__device__ __nv_bfloat16  g_whh[(size_t)G3 * HH];
__device__ __nv_bfloat16  g_whl[(size_t)G3 * HH];
__device__ unsigned g_rbits[TT];
__device__ unsigned g_poslist[NPOS];
__device__ unsigned g_waveoff[TT + 1];
__device__ unsigned g_nwaves;
__device__ unsigned g_bar;

// ---- packed fp32x2 helpers ----
__device__ __forceinline__ void fma2(u64& d, u64 a, u64 b) {
    asm("fma.rn.f32x2 %0, %1, %2, %0;" : "+l"(d) : "l"(a), "l"(b));
}
__device__ __forceinline__ u64 dup2(float x) {
    u64 r; asm("mov.b64 %0, {%1, %1};" : "=l"(r) : "f"(x)); return r;
}
__device__ __forceinline__ float2 unpk(u64 v) {
    float2 r; asm("mov.b64 {%0, %1}, %2;" : "=f"(r.x), "=f"(r.y) : "l"(v)); return r;
}
__device__ __forceinline__ float sigm(float x) {
    return 1.f / (1.f + __expf(-x));
}
__device__ __forceinline__ unsigned su32(const void* p) {
    unsigned a;
    asm("{ .reg .u64 t; cvta.to.shared.u64 t, %1; cvt.u32.u64 %0, t; }"
        : "=r"(a) : "l"(p));
    return a;
}

// ---- mma.sync helpers ----
__device__ __forceinline__ void ldm_x4(unsigned addr, unsigned r[4]) {
    asm volatile("ldmatrix.sync.aligned.m8n8.x4.shared.b16 {%0,%1,%2,%3}, [%4];"
        : "=r"(r[0]), "=r"(r[1]), "=r"(r[2]), "=r"(r[3]) : "r"(addr));
}
__device__ __forceinline__ void mma16816(float d[4], const unsigned a[4],
                                         unsigned b0, unsigned b1) {
    asm volatile(
        "mma.sync.aligned.m16n8k16.row.col.f32.bf16.bf16.f32 "
        "{%0,%1,%2,%3}, {%4,%5,%6,%7}, {%8,%9}, {%0,%1,%2,%3};"
        : "+f"(d[0]), "+f"(d[1]), "+f"(d[2]), "+f"(d[3])
        : "r"(a[0]), "r"(a[1]), "r"(a[2]), "r"(a[3]), "r"(b0), "r"(b1));
}

// ---------------------------------------------------------------------------
// prep: bf16 hi/lo splits of x, w_i^T, w_h^T
// ---------------------------------------------------------------------------
__global__ void prep_kernel(const float* __restrict__ x,
                            const float* __restrict__ w_i,
                            const float* __restrict__ w_h) {
    const size_t stride = (size_t)gridDim.x * blockDim.x;
    size_t i0 = (size_t)blockIdx.x * blockDim.x + threadIdx.x;
    for (size_t i = i0; i < (size_t)NPOS * HH; i += stride) {
        float v = x[i];
        __nv_bfloat16 h = __float2bfloat16(v);
        g_xh[i] = h;
        g_xl[i] = __float2bfloat16(v - __bfloat162float(h));
    }
    for (size_t i = i0; i < (size_t)G3 * HH; i += stride) {
        size_t k = i / G3, n = i % G3;
        float v = w_i[i];
        __nv_bfloat16 h = __float2bfloat16(v);
        g_wth[n * HH + k] = h;
        g_wtl[n * HH + k] = __float2bfloat16(v - __bfloat162float(h));
        float vh = w_h[i];
        __nv_bfloat16 hh = __float2bfloat16(vh);
        g_whh[n * HH + k] = hh;
        g_whl[n * HH + k] = __float2bfloat16(vh - __bfloat162float(hh));
    }
}

// ---------------------------------------------------------------------------
// gx via mma.sync bf16x3 (unchanged, validated)
// ---------------------------------------------------------------------------
#define STRD 40
#define GX_SMEM 81920

__global__ void __launch_bounds__(256, 1) gx_mma_kernel() {
    extern __shared__ __nv_bfloat16 sb[];
    const int tid = threadIdx.x;
    const int lane = tid & 31;
    const int wid = tid >> 5;
    const int wm = wid >> 1;
    const int wn = wid & 1;
    const int m0 = blockIdx.y * 128;
    const int n0 = blockIdx.x * 128;

    __nv_bfloat16* Ah = sb;
    __nv_bfloat16* Al = sb + 10240;
    __nv_bfloat16* Bh = sb + 20480;
    __nv_bfloat16* Bl = sb + 30720;
    const unsigned aAh = su32(Ah);
    const unsigned aBh = su32(Bh);

    float d[2][8][4];
#pragma unroll
    for (int mt = 0; mt < 2; mt++)
#pragma unroll
        for (int nt = 0; nt < 8; nt++)
#pragma unroll
            for (int j = 0; j < 4; j++) d[mt][nt][j] = 0.f;

    const unsigned aoff = (unsigned)(((lane & 15) * STRD + (lane >> 4) * 8) * 2);
    const unsigned boff = (unsigned)(((((lane & 7) + ((lane >> 4) << 3)) * STRD) +
                                     (((lane >> 3) & 1) * 8)) * 2);

    uint4 rah[2], ral[2], rbh[2], rbl[2];
    auto loadAB = [&](int kc0) {
#pragma unroll
        for (int p = 0; p < 2; p++) {
            int q = tid + 256 * p;
            int r = q >> 2, sg = q & 3;
            size_t offa = (size_t)(m0 + r) * HH + kc0 + sg * 8;
            size_t offb = (size_t)(n0 + r) * HH + kc0 + sg * 8;
            rah[p] = *(const uint4*)(g_xh + offa);
            ral[p] = *(const uint4*)(g_xl + offa);
            rbh[p] = *(const uint4*)(g_wth + offb);
            rbl[p] = *(const uint4*)(g_wtl + offb);
        }
    };
    auto storeAB = [&](int buf) {
#pragma unroll
        for (int p = 0; p < 2; p++) {
            int q = tid + 256 * p;
            int r = q >> 2, sg = q & 3;
            int so = buf * 5120 + r * STRD + sg * 8;
            *(uint4*)(Ah + so) = rah[p];
            *(uint4*)(Al + so) = ral[p];
            *(uint4*)(Bh + so) = rbh[p];
            *(uint4*)(Bl + so) = rbl[p];
        }
    };

    loadAB(0);
    storeAB(0);

    for (int ch = 0; ch < 32; ch++) {
        __syncthreads();
        const int db = ch & 1;
        if (ch < 31) loadAB((ch + 1) * 32);

#pragma unroll
        for (int ks = 0; ks < 2; ks++) {
            unsigned ah[2][4], al[2][4];
#pragma unroll
            for (int mt = 0; mt < 2; mt++) {
                unsigned base = aAh + (unsigned)(db * 10240 +
                                (wm * 32 + mt * 16) * 80 + ks * 32) + aoff;
                ldm_x4(base, ah[mt]);
                ldm_x4(base + 20480u, al[mt]);
            }
#pragma unroll
            for (int bt = 0; bt < 4; bt++) {
                unsigned bh[4], bl[4];
                unsigned baseb = aBh + (unsigned)(db * 10240 +
                                 (wn * 64 + bt * 16) * 80 + ks * 32) + boff;
                ldm_x4(baseb, bh);
                ldm_x4(baseb + 20480u, bl);
#pragma unroll
                for (int mt = 0; mt < 2; mt++) {
                    mma16816(d[mt][bt * 2],     ah[mt], bh[0], bh[1]);
                    mma16816(d[mt][bt * 2],     ah[mt], bl[0], bl[1]);
                    mma16816(d[mt][bt * 2],     al[mt], bh[0], bh[1]);
                    mma16816(d[mt][bt * 2 + 1], ah[mt], bh[2], bh[3]);
                    mma16816(d[mt][bt * 2 + 1], ah[mt], bl[2], bl[3]);
                    mma16816(d[mt][bt * 2 + 1], al[mt], bh[2], bh[3]);
                }
            }
        }
        if (ch < 31) storeAB(db ^ 1);
    }

#pragma unroll
    for (int mt = 0; mt < 2; mt++) {
        int row = m0 + wm * 32 + mt * 16 + (lane >> 2);
#pragma unroll
        for (int nt = 0; nt < 8; nt++) {
            int col = n0 + wn * 64 + nt * 8 + (lane & 3) * 2;
            float* p0 = g_gx + (size_t)row * G3 + col;
            *(float2*)p0            = make_float2(d[mt][nt][0], d[mt][nt][1]);
            *(float2*)(p0 + 8 * G3) = make_float2(d[mt][nt][2], d[mt][nt][3]);
        }
    }
}

// ---------------------------------------------------------------------------
// setup (unchanged)
// ---------------------------------------------------------------------------
__global__ void setup_kernel(const void* __restrict__ reset_raw,
                             const float* __restrict__ initial_h,
                             float* __restrict__ out) {
    __shared__ unsigned hist[TT];
    __shared__ unsigned curs[TT];
    __shared__ unsigned rbs[TT];
    __shared__ unsigned short depth[NB][TT];
    __shared__ int s_i32, s_f32;
    const int tid = threadIdx.x;
    if (tid == 0) { s_i32 = 1; s_f32 = 1; }
    __syncthreads();
    {
        const unsigned* rw = (const unsigned*)reset_raw;
        int bad_i = 0, bad_f = 0;
        for (int q = tid; q < 4096; q += 256) {
            unsigned v = rw[q];
            if (v > 1u) bad_i = 1;
            if (v != 0u && v != 0x3F800000u) bad_f = 1;
        }
        if (bad_i) s_i32 = 0;
        if (bad_f) s_f32 = 0;
    }
    __syncthreads();
    const int rmode = s_i32 ? 0 : (s_f32 ? 1 : 2);
    const int*           r32 = (const int*)reset_raw;
    const float*         rf  = (const float*)reset_raw;
    const unsigned char* r8  = (const unsigned char*)reset_raw;

    for (int t = tid; t < TT; t += 256) {
        unsigned m = 0;
#pragma unroll
        for (int n = 0; n < NB; n++) {
            bool rv = (rmode == 0) ? (r32[n * TT + t] != 0)
                    : (rmode == 1) ? (rf[n * TT + t] != 0.f)
                                   : (r8[n * TT + t] != 0);
            m |= (unsigned)rv << n;
        }
        rbs[t] = m;
        g_rbits[t] = m;
        hist[t] = 0;
    }
    __syncthreads();
    if (tid < NB) {
        unsigned short d = 0;
        for (int t = 0; t < TT; t++) {
            if (t == 0 || ((rbs[t] >> tid) & 1u)) d = 0; else d++;
            depth[tid][t] = d;
            atomicAdd(&hist[d], 1u);
        }
    }
    __syncthreads();
    if (tid == 0) {
        unsigned acc = 0, maxd = 0;
        for (int w0 = 0; w0 < TT; w0++) {
            unsigned c = hist[w0];
            if (c) maxd = (unsigned)w0;
            curs[w0] = acc;
            g_waveoff[w0] = acc;
            acc += c;
        }
        g_waveoff[TT] = acc;
        g_nwaves = maxd + 1;
        g_bar = 0u;
    }
    __syncthreads();
    for (int p = tid; p < NPOS; p += 256) {
        int n = p >> 10, t = p & 1023;
        unsigned d = depth[n][t];
        unsigned slot = atomicAdd(&curs[d], 1u);
        g_poslist[slot] = (unsigned)p;
    }
    for (int q = tid; q < HH; q += 256)
        out[2 * (size_t)NTH_ELEMS + q] = initial_h[q];
}

// ---------------------------------------------------------------------------
__device__ __forceinline__ void grid_barrier(unsigned target) {
    __syncthreads();
    if (threadIdx.x == 0) {
        asm volatile("red.release.gpu.global.add.u32 [%0], 1;"
                     :: "l"(&g_bar) : "memory");
        unsigned v;
        do {
            asm volatile("ld.acquire.gpu.global.u32 %0, [%1];"
                         : "=r"(v) : "l"(&g_bar) : "memory");
        } while (v < target);
    }
    __syncthreads();
}

// ---------------------------------------------------------------------------
struct WaveCtx {
    const float* carry;
    const float* initial_h;
    const float* w_h;
    const float* bias;
    float* out;
    float* AsRaw;
    float (*Bs)[32][128];
    const unsigned* rbs;
    const float** rowp;
    unsigned* posv;
};

__device__ __forceinline__ void set_rows(const WaveCtx& C, int phase,
                                         int mtile, int POSB,
                                         unsigned base, unsigned cnt) {
    const int tid = threadIdx.x;
    __syncthreads();
    if (tid < POSB) {
        int idx = mtile * POSB + tid;
        unsigned pos = 0xFFFFFFFFu;
        const float* rp = C.initial_h;
        if ((unsigned)idx < cnt) {
            pos = g_poslist[base + idx];
            int n = pos >> 10, t = (int)(pos & 1023);
            if (phase)
                rp = g_rh + (size_t)pos * HH;
            else if ((C.rbs[t] >> n) & 1u)
                rp = C.initial_h;
            else if (t == 0)
                rp = C.carry + (size_t)n * TT * HH;
            else
                rp = C.out + (size_t)(pos - 1) * HH;
        }
        C.posv[tid] = pos;
        C.rowp[tid] = rp;
    }
    __syncthreads();
}

__device__ __forceinline__ void epi_pair(const WaveCtx& C, int phase,
                                         unsigned pos, int col0,
                                         const float* rowptr,
                                         float res0, float res1) {
    float2 gx = __ldcg((const float2*)(g_gx + (size_t)pos * G3 + col0));
    float2 bb = *(const float2*)(C.bias + col0);
    if (phase == 0 && col0 < HH) {
        float z0 = sigm(gx.x + res0 + bb.x);
        float z1 = sigm(gx.y + res1 + bb.y);
        *(float2*)(g_z + (size_t)pos * HH + col0) = make_float2(z0, z1);
    } else if (phase == 0) {
        const int j0 = col0 - HH;
        float2 h = __ldcg((const float2*)(rowptr + j0));
        float r0 = sigm(gx.x + res0 + bb.x);
        float r1 = sigm(gx.y + res1 + bb.y);
        *(float2*)(g_rh + (size_t)pos * HH + j0) =
            make_float2(r0 * h.x, r1 * h.y);
    } else {
        const int j0 = col0 - 2 * HH;
        int n = pos >> 10, t = (int)(pos & 1023);
        const float* hp = ((C.rbs[t] >> n) & 1u) ? C.initial_h
                        : (t == 0 ? C.carry + (size_t)n * TT * HH
                                  : C.out + (size_t)(pos - 1) * HH);
        float2 h = __ldcg((const float2*)(hp + j0));
        float2 z = __ldcg((const float2*)(g_z + (size_t)pos * HH + j0));
        float a0 = tanhf(gx.x + res0 + bb.x);
        float a1 = tanhf(gx.y + res1 + bb.y);
        float o0 = (1.f - z.x) * h.x + z.x * a0;
        float o1 = (1.f - z.y) * h.y + z.y * a1;
        float* op = C.out + (size_t)pos * HH + j0;
        *(float2*)op               = make_float2(o0, o1);
        *(float2*)(op + NTH_ELEMS) = make_float2(o0, o1);
    }
}

__device__ __forceinline__ void epi_seg(const WaveCtx& C, int phase,
                                        unsigned pos, int col0,
                                        const float* rowptr,
                                        u64 q0, u64 q1) {
    float2 f0 = unpk(q0), f1 = unpk(q1);
    epi_pair(C, phase, pos, col0,     rowptr, f0.x, f0.y);
    epi_pair(C, phase, pos, col0 + 2, rowptr, f1.x, f1.y);
}

// ---------------------------------------------------------------------------
// MMA tile (bf16x3): MR gathered rows x 128 cols, K=1024, chunk=16, 2-buf
// MR=128: warp 32m x 64n (R13-identical).  MR=64: warp 32m x 32n.
// ---------------------------------------------------------------------------
#define MSTRD 24
template<int MR>
__device__ void gemm_mma(const WaveCtx& C, int phase, int mtile, int ntile,
                         unsigned base, unsigned cnt) {
    constexpr int WN   = (MR == 128) ? 2 : 4;
    constexpr int NEXT = 128 / WN;          // 64 or 32
    constexpr int NT   = NEXT / 16;         // 4 or 2
    const int tid = threadIdx.x;
    const int lane = tid & 31;
    const int wid = tid >> 5;
    const int wm = (MR == 128) ? (wid >> 1) : (wid >> 2);
    const int wn = wid & (WN - 1);

    set_rows(C, phase, mtile, MR, base, cnt);

    const int colbase = (phase ? 2 * HH : 0) + ntile * 128;

    __nv_bfloat16* Ah = (__nv_bfloat16*)C.AsRaw;
    const unsigned aAh = su32(Ah);
    // element offsets: Al = MR*48, Bh = MR*96, Bl = MR*96 + 6144
    // byte offsets for ldmatrix: Al = +MR*96, B base = +MR*192, Bl = +12288

    float d[2][NT][4];
#pragma unroll
    for (int mt = 0; mt < 2; mt++)
#pragma unroll
        for (int nt = 0; nt < NT; nt++)
#pragma unroll
            for (int j = 0; j < 4; j++) d[mt][nt][j] = 0.f;

    const unsigned aoff = (unsigned)((lane & 15) * (MSTRD * 2) + (lane >> 4) * 16);
    const unsigned boff = (unsigned)((((lane & 7) + ((lane >> 4) << 3)) * (MSTRD * 2)) +
                                     (((lane >> 3) & 1) * 16));

    const int r  = tid >> 1;       // A row (0..127 / 0..63) and B row (0..127)
    const int sg = tid & 1;
    const bool doA = (MR == 128) || (tid < 128);
    const __nv_bfloat16* bsrc_h = g_whh + (size_t)(colbase + r) * HH + sg * 8;
    const __nv_bfloat16* bsrc_l = g_whl + (size_t)(colbase + r) * HH + sg * 8;

    float4 fa0, fa1;
    uint4 rbh, rbl;
    auto loadChunk = [&](int k0) {
        if (doA) {
            fa0 = __ldcg((const float4*)(C.rowp[r] + k0 + sg * 8));
            fa1 = __ldcg((const float4*)(C.rowp[r] + k0 + sg * 8 + 4));
        }
        rbh = __ldcg((const uint4*)(bsrc_h + k0));
        rbl = __ldcg((const uint4*)(bsrc_l + k0));
    };
    auto storeChunk = [&](int buf) {
        if (doA) {
            float fa[8] = {fa0.x, fa0.y, fa0.z, fa0.w, fa1.x, fa1.y, fa1.z, fa1.w};
            __align__(16) __nv_bfloat16 hh[8], ll[8];
#pragma unroll
            for (int s = 0; s < 8; s++) {
                __nv_bfloat16 h = __float2bfloat16(fa[s]);
                hh[s] = h;
                ll[s] = __float2bfloat16(fa[s] - __bfloat162float(h));
            }
            int so = buf * (MR * MSTRD) + r * MSTRD + sg * 8;
            *(uint4*)(Ah + so)           = *(const uint4*)hh;
            *(uint4*)(Ah + MR * 48 + so) = *(const uint4*)ll;
        }
        int sob = buf * 3072 + r * MSTRD + sg * 8;
        *(uint4*)(Ah + MR * 96 + sob)        = rbh;
        *(uint4*)(Ah + MR * 96 + 6144 + sob) = rbl;
    };

    loadChunk(0);
    storeChunk(0);

    for (int ch = 0; ch < 64; ch++) {
        __syncthreads();
        const int db = ch & 1;
        if (ch < 63) loadChunk((ch + 1) * 16);

        unsigned ah[2][4], al[2][4];
#pragma unroll
        for (int mt = 0; mt < 2; mt++) {
            unsigned ba = aAh + (unsigned)(db * (MR * 48) +
                          (wm * 32 + mt * 16) * (MSTRD * 2)) + aoff;
            ldm_x4(ba, ah[mt]);
            ldm_x4(ba + (unsigned)(MR * 96), al[mt]);
        }
#pragma unroll
        for (int bt = 0; bt < NT; bt++) {
            unsigned bh4[4], bl4[4];
            unsigned bb = aAh + (unsigned)(MR * 192) + (unsigned)(db * 6144 +
                          (wn * NEXT + bt * 16) * (MSTRD * 2)) + boff;
            ldm_x4(bb, bh4);
            ldm_x4(bb + 12288u, bl4);
#pragma unroll
            for (int mt = 0; mt < 2; mt++) {
                mma16816(d[mt][bt],     ah[mt], bh4[0], bh4[1]);
                mma16816(d[mt][bt],     ah[mt], bl4[0], bl4[1]);
                mma16816(d[mt][bt],     al[mt], bh4[0], bh4[1]);
            }
            // second 8-col subtile uses bh4[2],bh4[3]
#pragma unroll
            for (int mt = 0; mt < 2; mt++) {
                mma16816(d[mt][bt] + 0, ah[mt], bh4[2], bh4[3]);   // placeholder
            }
        }
        if (ch < 63) storeChunk(db ^ 1);
    }

    // (unreachable placeholder fix below)
}

// NOTE: the loop above needs separate accumulators for the two 8-col subtiles
// per bt; specialization with correct accumulator shape:
template<int MR>
__device__ void gemm_mma_real(const WaveCtx& C, int phase, int mtile, int ntile,
                              unsigned base, unsigned cnt) {
    constexpr int WN   = (MR == 128) ? 2 : 4;
    constexpr int NEXT = 128 / WN;          // 64 or 32
    constexpr int NT   = NEXT / 16;         // 4 or 2
    const int tid = threadIdx.x;
    const int lane = tid & 31;
    const int wid = tid >> 5;
    const int wm = (MR == 128) ? (wid >> 1) : (wid >> 2);
    const int wn = wid & (WN - 1);

    set_rows(C, phase, mtile, MR, base, cnt);

    const int colbase = (phase ? 2 * HH : 0) + ntile * 128;

    __nv_bfloat16* Ah = (__nv_bfloat16*)C.AsRaw;
    const unsigned aAh = su32(Ah);

    float d[2][2 * NT][4];
#pragma unroll
    for (int mt = 0; mt < 2; mt++)
#pragma unroll
        for (int nt = 0; nt < 2 * NT; nt++)
#pragma unroll
            for (int j = 0; j < 4; j++) d[mt][nt][j] = 0.f;

    const unsigned aoff = (unsigned)((lane & 15) * (MSTRD * 2) + (lane >> 4) * 16);
    const unsigned boff = (unsigned)((((lane & 7) + ((lane >> 4) << 3)) * (MSTRD * 2)) +
                                     (((lane >> 3) & 1) * 16));

    const int r  = tid >> 1;
    const int sg = tid & 1;
    const bool doA = (MR == 128) || (tid < 128);
    const __nv_bfloat16* bsrc_h = g_whh + (size_t)(colbase + r) * HH + sg * 8;
    const __nv_bfloat16* bsrc_l = g_whl + (size_t)(colbase + r) * HH + sg * 8;

    float4 fa0, fa1;
    uint4 rbh, rbl;
    auto loadChunk = [&](int k0) {
        if (doA) {
            fa0 = __ldcg((const float4*)(C.rowp[r] + k0 + sg * 8));
            fa1 = __ldcg((const float4*)(C.rowp[r] + k0 + sg * 8 + 4));
        }
        rbh = __ldcg((const uint4*)(bsrc_h + k0));
        rbl = __ldcg((const uint4*)(bsrc_l + k0));
    };
    auto storeChunk = [&](int buf) {
        if (doA) {
            float fa[8] = {fa0.x, fa0.y, fa0.z, fa0.w, fa1.x, fa1.y, fa1.z, fa1.w};
            __align__(16) __nv_bfloat16 hh[8], ll[8];
#pragma unroll
            for (int s = 0; s < 8; s++) {
                __nv_bfloat16 h = __float2bfloat16(fa[s]);
                hh[s] = h;
                ll[s] = __float2bfloat16(fa[s] - __bfloat162float(h));
            }
            int so = buf * (MR * MSTRD) + r * MSTRD + sg * 8;
            *(uint4*)(Ah + so)           = *(const uint4*)hh;
            *(uint4*)(Ah + MR * 48 + so) = *(const uint4*)ll;
        }
        int sob = buf * 3072 + r * MSTRD + sg * 8;
        *(uint4*)(Ah + MR * 96 + sob)        = rbh;
        *(uint4*)(Ah + MR * 96 + 6144 + sob) = rbl;
    };

    loadChunk(0);
    storeChunk(0);

    for (int ch = 0; ch < 64; ch++) {
        __syncthreads();
        const int db = ch & 1;
        if (ch < 63) loadChunk((ch + 1) * 16);

        unsigned ah[2][4], al[2][4];
#pragma unroll
        for (int mt = 0; mt < 2; mt++) {
            unsigned ba = aAh + (unsigned)(db * (MR * 48) +
                          (wm * 32 + mt * 16) * (MSTRD * 2)) + aoff;
            ldm_x4(ba, ah[mt]);
            ldm_x4(ba + (unsigned)(MR * 96), al[mt]);
        }
#pragma unroll
        for (int bt = 0; bt < NT; bt++) {
            unsigned bh4[4], bl4[4];
            unsigned bb = aAh + (unsigned)(MR * 192) + (unsigned)(db * 6144 +
                          (wn * NEXT + bt * 16) * (MSTRD * 2)) + boff;
            ldm_x4(bb, bh4);
            ldm_x4(bb + 12288u, bl4);
#pragma unroll
            for (int mt = 0; mt < 2; mt++) {
                mma16816(d[mt][bt * 2],     ah[mt], bh4[0], bh4[1]);
                mma16816(d[mt][bt * 2],     ah[mt], bl4[0], bl4[1]);
                mma16816(d[mt][bt * 2],     al[mt], bh4[0], bh4[1]);
                mma16816(d[mt][bt * 2 + 1], ah[mt], bh4[2], bh4[3]);
                mma16816(d[mt][bt * 2 + 1], ah[mt], bl4[2], bl4[3]);
                mma16816(d[mt][bt * 2 + 1], al[mt], bh4[2], bh4[3]);
            }
        }
        if (ch < 63) storeChunk(db ^ 1);
    }

    // epilogue
#pragma unroll
    for (int mt = 0; mt < 2; mt++) {
#pragma unroll
        for (int half = 0; half < 2; half++) {
            const int i = wm * 32 + mt * 16 + (lane >> 2) + half * 8;
            unsigned pos = C.posv[i];
            if (pos == 0xFFFFFFFFu) continue;
            const float* rp = C.rowp[i];
#pragma unroll
            for (int nt = 0; nt < 2 * NT; nt++) {
                int col = colbase + wn * NEXT + nt * 8 + (lane & 3) * 2;
                epi_pair(C, phase, pos, col, rp,
                         d[mt][nt][half * 2], d[mt][nt][half * 2 + 1]);
            }
        }
    }
}

// ---------------------------------------------------------------------------
// small tile: FFMA2 16 rows (unchanged R1)
// ---------------------------------------------------------------------------
__device__ void gemm_tile1(const WaveCtx& C, int phase, int mtile, int ntile,
                           unsigned base, unsigned cnt) {
    const int tid = threadIdx.x;
    const int tx = tid & 15;
    const int ty = tid >> 4;
    float (*As)[32][64] = (float(*)[32][64])C.AsRaw;

    set_rows(C, phase, mtile, 16, base, cnt);

    const int colbase = (phase ? 2 * HH : 0) + ntile * 128;
    const float* wb = C.w_h + colbase;

    u64 acc[4];
#pragma unroll
    for (int j = 0; j < 4; j++) acc[j] = 0ull;

    float4 aL, bL[4];
    auto loadA = [&](int k0) {
        if (tid < 128) {
            int i = tid & 15, kc = tid >> 4;
            aL = __ldcg((const float4*)(C.rowp[i] + k0 + kc * 4));
        }
    };
    auto storeA = [&](int buf) {
        if (tid < 128) {
            int i = tid & 15, kc = tid >> 4;
            As[buf][kc * 4 + 0][i] = aL.x;
            As[buf][kc * 4 + 1][i] = aL.y;
            As[buf][kc * 4 + 2][i] = aL.z;
            As[buf][kc * 4 + 3][i] = aL.w;
        }
    };
    auto loadB = [&](int k0) {
#pragma unroll
        for (int c = 0; c < 4; c++) {
            int q = tid + 256 * c;
            int row = q >> 5, c4 = q & 31;
            bL[c] = __ldcg((const float4*)(wb + (size_t)(k0 + row) * G3 + c4 * 4));
        }
    };
    auto storeB = [&](int buf) {
#pragma unroll
        for (int c = 0; c < 4; c++) {
            int q = tid + 256 * c;
            int row = q >> 5, c4 = q & 31;
            *(float4*)&C.Bs[buf][row][c4 * 4] = bL[c];
        }
    };

    loadA(0); loadB(0);
    storeA(0); storeB(0);
    for (int it = 0; it < 32; it++) {
        __syncthreads();
        const int db = it & 1;
        if (it < 31) { loadA((it + 1) * 32); loadB((it + 1) * 32); }
#pragma unroll
        for (int kk = 0; kk < 32; kk++) {
            float av = As[db][kk][ty];
            ulonglong2 b01 = *(const ulonglong2*)&C.Bs[db][kk][tx * 4];
            ulonglong2 b23 = *(const ulonglong2*)&C.Bs[db][kk][64 + tx * 4];
            u64 ar = dup2(av);
            fma2(acc[0], ar, b01.x);
            fma2(acc[1], ar, b01.y);
            fma2(acc[2], ar, b23.x);
            fma2(acc[3], ar, b23.y);
        }
        if (it < 31) { const int nb = db ^ 1; storeA(nb); storeB(nb); }
    }

    unsigned pos = C.posv[ty];
    if (pos != 0xFFFFFFFFu) {
        epi_seg(C, phase, pos, colbase + tx * 4,      C.rowp[ty], acc[0], acc[1]);
        epi_seg(C, phase, pos, colbase + 64 + tx * 4, C.rowp[ty], acc[2], acc[3]);
    }
}

// ---------------------------------------------------------------------------
__global__ void __launch_bounds__(WTHR, 2) wave_kernel(
        const float* __restrict__ carry,
        const float* __restrict__ initial_h,
        const float* __restrict__ w_h,
        const float* __restrict__ bias,
        float* __restrict__ out) {
    extern __shared__ char smw[];
    WaveCtx C;
    C.AsRaw = (float*)smw;
    C.Bs    = (float(*)[32][128])(smw + 16896);
    unsigned* rbs = (unsigned*)(smw + 49664);
    C.rowp  = (const float**)(smw + 53760);
    C.posv  = (unsigned*)(smw + 54784);
    C.rbs = rbs;
    C.carry = carry; C.initial_h = initial_h;
    C.w_h = w_h; C.bias = bias; C.out = out;

    const int tid = threadIdx.x;
    for (int t = tid; t < TT; t += WTHR) rbs[t] = g_rbits[t];
    __syncthreads();

    const unsigned nw = g_nwaves;
    unsigned bar_t = 0;

    for (unsigned wv = 0; wv < nw; wv++) {
        const unsigned base = g_waveoff[wv];
        const unsigned cnt  = g_waveoff[wv + 1] - base;
        const int kind = (cnt >= 1536) ? 2 : (cnt >= 128 ? 1 : 0);
        const int mt = (kind == 2) ? (int)((cnt + 127) >> 7)
                     : (kind == 1) ? (int)((cnt + 63) >> 6)
                                   : (int)((cnt + 15) >> 4);

        for (int tile = blockIdx.x; tile < mt * 16; tile += NCTA_W) {
            if (kind == 2)      gemm_mma_real<128>(C, 0, tile >> 4, tile & 15, base, cnt);
            else if (kind == 1) gemm_mma_real<64>(C, 0, tile >> 4, tile & 15, base, cnt);
            else                gemm_tile1(C, 0, tile >> 4, tile & 15, base, cnt);
        }
        bar_t += NCTA_W;
        grid_barrier(bar_t);

        for (int tile = blockIdx.x; tile < mt * 8; tile += NCTA_W) {
            if (kind == 2)      gemm_mma_real<128>(C, 1, tile >> 3, tile & 7, base, cnt);
            else if (kind == 1) gemm_mma_real<64>(C, 1, tile >> 3, tile & 7, base, cnt);
            else                gemm_tile1(C, 1, tile >> 3, tile & 7, base, cnt);
        }
        bar_t += NCTA_W;
        grid_barrier(bar_t);
    }
}

// ---------------------------------------------------------------------------
extern "C" void kernel_launch(void* const* d_in, const int* in_sizes, int n_in,
                              void* d_out, int out_size) {
    const float* x         = (const float*)d_in[0];
    const void*  reset     = d_in[1];
    const float* carry     = (const float*)d_in[2];
    const float* initial_h = (const float*)d_in[3];
    const float* w_i       = (const float*)d_in[4];
    const float* w_h       = (const float*)d_in[5];
    const float* b         = (const float*)d_in[6];
    float*       out       = (float*)d_out;
    (void)in_sizes; (void)n_in; (void)out_size;

    prep_kernel<<<2048, 256>>>(x, w_i, w_h);

    cudaFuncSetAttribute((const void*)gx_mma_kernel,
                         cudaFuncAttributeMaxDynamicSharedMemorySize, GX_SMEM);
    dim3 tgrid(G3 / 128, NPOS / 128);
    gx_mma_kernel<<<tgrid, 256, GX_SMEM>>>();

    setup_kernel<<<1, 256>>>(reset, initial_h, out);

    size_t smem = 55296;
    cudaFuncSetAttribute((const void*)wave_kernel,
                         cudaFuncAttributeMaxDynamicSharedMemorySize, (int)smem);
    wave_kernel<<<NCTA_W, WTHR, smem>>>(carry, initial_h, w_h, b, out);
}